// round 4
// baseline (speedup 1.0000x reference)
#include <cuda_runtime.h>
#include <cstddef>

#define N_NODES 100000
#define F_DIM   256
#define NNZ     1600000
#define NB1     98          // ceil(N_NODES/1024)

// ---------------- scratch (no allocation allowed) ----------------
// __device__ symbols are ONLY referenced from device code, never passed
// as kernel arguments from host.
__device__ float g_xt[(size_t)N_NODES * F_DIM];  // GEMM output (both layers)
__device__ float g_m [(size_t)N_NODES * F_DIM];  // hyperedge accumulator
__device__ float g_h [(size_t)N_NODES * F_DIM];  // layer-1 hidden

__device__ int g_degD[N_NODES];
__device__ int g_degB[N_NODES];
__device__ int g_offD[N_NODES];
__device__ int g_offB[N_NODES];
__device__ int g_curD[N_NODES];
__device__ int g_curB[N_NODES];
__device__ int g_adjD[NNZ];       // grouped by src: stores dst ids
__device__ int g_adjB[NNZ];       // grouped by dst: stores src ids
__device__ int g_bsumD[NB1];
__device__ int g_bsumB[NB1];

// ---------------- CSR build ----------------
__global__ void k_zero_counts() {
    int i = blockIdx.x * blockDim.x + threadIdx.x;
    if (i < N_NODES) { g_degD[i] = 0; g_degB[i] = 0; }
}

__global__ void k_count(const int* __restrict__ ei) {
    int i = blockIdx.x * blockDim.x + threadIdx.x;
    if (i < NNZ) {
        atomicAdd(&g_degD[ei[i]], 1);
        atomicAdd(&g_degB[ei[i + NNZ]], 1);
    }
}

// per-block exclusive scan of 1024 elems; blockIdx.y: 0 -> D, 1 -> B
__global__ void k_scan1() {
    int which = blockIdx.y;
    const int* __restrict__ in  = which ? g_degB  : g_degD;
    int* __restrict__ out       = which ? g_offB  : g_offD;
    int* __restrict__ bsums     = which ? g_bsumB : g_bsumD;
    __shared__ int sh[1024];
    int g = blockIdx.x * 1024 + threadIdx.x;
    int v = (g < N_NODES) ? in[g] : 0;
    sh[threadIdx.x] = v;
    __syncthreads();
    #pragma unroll
    for (int off = 1; off < 1024; off <<= 1) {
        int t = (threadIdx.x >= off) ? sh[threadIdx.x - off] : 0;
        __syncthreads();
        sh[threadIdx.x] += t;
        __syncthreads();
    }
    if (g < N_NODES) out[g] = sh[threadIdx.x] - v;   // exclusive
    if (threadIdx.x == 1023) bsums[blockIdx.x] = sh[1023];
}

__global__ void k_scan2() {
    int* __restrict__ bsums = blockIdx.y ? g_bsumB : g_bsumD;
    __shared__ int sh[128];
    int v = (threadIdx.x < NB1) ? bsums[threadIdx.x] : 0;
    sh[threadIdx.x] = v;
    __syncthreads();
    #pragma unroll
    for (int off = 1; off < 128; off <<= 1) {
        int t = (threadIdx.x >= off) ? sh[threadIdx.x - off] : 0;
        __syncthreads();
        sh[threadIdx.x] += t;
        __syncthreads();
    }
    if (threadIdx.x < NB1) bsums[threadIdx.x] = sh[threadIdx.x] - v;
}

__global__ void k_scan3() {
    int which = blockIdx.y;
    int* __restrict__ out         = which ? g_offB  : g_offD;
    const int* __restrict__ bsums = which ? g_bsumB : g_bsumD;
    int* __restrict__ cur         = which ? g_curB  : g_curD;
    int g = blockIdx.x * 1024 + threadIdx.x;
    if (g < N_NODES) {
        int v = out[g] + bsums[blockIdx.x];
        out[g] = v;
        cur[g] = v;
    }
}

__global__ void k_fill(const int* __restrict__ ei) {
    int i = blockIdx.x * blockDim.x + threadIdx.x;
    if (i < NNZ) {
        int s = ei[i], d = ei[i + NNZ];
        g_adjD[atomicAdd(&g_curD[s], 1)] = d;
        g_adjB[atomicAdd(&g_curB[d], 1)] = s;
    }
}

// ---------------- fp32 SGEMM with packed f32x2 FMA ----------------
// g_xt = A[N,256] @ W[256,256]
#define GBM 128
#define GBN 128
#define GBK 16

__device__ __forceinline__ void ffma2(unsigned long long& d,
                                      unsigned long long a,
                                      unsigned long long b) {
    asm("fma.rn.f32x2 %0, %1, %2, %0;" : "+l"(d) : "l"(a), "l"(b));
}

__global__ __launch_bounds__(256)
void k_gemm(const float* __restrict__ A_ext, const float* __restrict__ W, int use_h) {
    // As stores element-DUPLICATED pairs: As[k][2m] = As[k][2m+1] = A[bm+m][k0+k]
    // so one LDS.128 yields two broadcast f32x2 pairs (a_i,a_i),(a_{i+1},a_{i+1}).
    __shared__ float As[GBK][2 * GBM];   // 16 KB
    __shared__ float Bs[GBK][GBN];       // 8 KB
    const float* __restrict__ A = use_h ? g_h : A_ext;   // device-side select
    float* __restrict__ C = g_xt;

    int bm = blockIdx.y * GBM;
    int bn = blockIdx.x * GBN;
    int tid = threadIdx.x;
    int tx = tid & 15;    // 0..15 -> 8 cols each
    int ty = tid >> 4;    // 0..15 -> 8 rows each

    unsigned long long acc[8][4];   // acc[i][j] = packed (c[i][2j], c[i][2j+1])
    #pragma unroll
    for (int i = 0; i < 8; ++i)
        #pragma unroll
        for (int j = 0; j < 4; ++j) acc[i][j] = 0ull;

    for (int k0 = 0; k0 < F_DIM; k0 += GBK) {
        // A tile 128x16 -> As duplicated-transposed: 512 float4, 2 per thread
        #pragma unroll
        for (int l = 0; l < 2; ++l) {
            int idx = tid + l * 256;
            int r  = idx >> 2;           // 0..127 (m)
            int c4 = (idx & 3) << 2;     // 0,4,8,12 (k)
            int grow = bm + r;
            float4 v = make_float4(0.f, 0.f, 0.f, 0.f);
            if (grow < N_NODES)
                v = *(const float4*)(A + (size_t)grow * F_DIM + k0 + c4);
            *(float2*)&As[c4 + 0][2 * r] = make_float2(v.x, v.x);
            *(float2*)&As[c4 + 1][2 * r] = make_float2(v.y, v.y);
            *(float2*)&As[c4 + 2][2 * r] = make_float2(v.z, v.z);
            *(float2*)&As[c4 + 3][2 * r] = make_float2(v.w, v.w);
        }
        // B tile 16x128: 512 float4, 2 per thread
        #pragma unroll
        for (int l = 0; l < 2; ++l) {
            int idx = tid + l * 256;
            int r  = idx >> 5;           // 0..15
            int c4 = (idx & 31) << 2;    // 0..124
            *(float4*)&Bs[r][c4] =
                *(const float4*)(W + (size_t)(k0 + r) * F_DIM + bn + c4);
        }
        __syncthreads();

        #pragma unroll
        for (int kk = 0; kk < GBK; ++kk) {
            // 4 LDS.128 -> 8 broadcast pairs (a_i,a_i)
            ulonglong2 a01 = *(const ulonglong2*)&As[kk][2 * (ty * 8) + 0];
            ulonglong2 a23 = *(const ulonglong2*)&As[kk][2 * (ty * 8) + 4];
            ulonglong2 a45 = *(const ulonglong2*)&As[kk][2 * (ty * 8) + 8];
            ulonglong2 a67 = *(const ulonglong2*)&As[kk][2 * (ty * 8) + 12];
            // 2 LDS.128 -> 4 natural pairs (b_{2j}, b_{2j+1})
            ulonglong2 b01 = *(const ulonglong2*)&Bs[kk][tx * 8];
            ulonglong2 b23 = *(const ulonglong2*)&Bs[kk][tx * 8 + 4];

            unsigned long long av[8] = {a01.x, a01.y, a23.x, a23.y,
                                        a45.x, a45.y, a67.x, a67.y};
            unsigned long long bv[4] = {b01.x, b01.y, b23.x, b23.y};
            #pragma unroll
            for (int i = 0; i < 8; ++i)
                #pragma unroll
                for (int j = 0; j < 4; ++j)
                    ffma2(acc[i][j], av[i], bv[j]);
        }
        __syncthreads();
    }

    #pragma unroll
    for (int i = 0; i < 8; ++i) {
        int grow = bm + ty * 8 + i;
        if (grow < N_NODES) {
            float* crow = C + (size_t)grow * F_DIM + bn + tx * 8;
            float2 p0 = *(float2*)&acc[i][0];
            float2 p1 = *(float2*)&acc[i][1];
            float2 p2 = *(float2*)&acc[i][2];
            float2 p3 = *(float2*)&acc[i][3];
            *(float4*)crow       = make_float4(p0.x, p0.y, p1.x, p1.y);
            *(float4*)(crow + 4) = make_float4(p2.x, p2.y, p3.x, p3.y);
        }
    }
}

// ------- gather node -> hyperedge: g_m[e] = Binv[e] * sum_{src in e} g_xt[src]
__global__ __launch_bounds__(256)
void k_gather_n2e() {
    int w = (blockIdx.x * blockDim.x + threadIdx.x) >> 5;
    if (w >= N_NODES) return;
    int lane = threadIdx.x & 31;
    int off = g_offB[w];
    int deg = g_degB[w];
    const int* __restrict__ adj = g_adjB + off;

    float4 a0 = make_float4(0.f, 0.f, 0.f, 0.f);
    float4 a1 = make_float4(0.f, 0.f, 0.f, 0.f);
    #pragma unroll 4
    for (int j = 0; j < deg; ++j) {
        int s = __ldg(adj + j);
        const float4* r = (const float4*)(g_xt + (size_t)s * F_DIM);
        float4 v0 = __ldg(r + lane);
        float4 v1 = __ldg(r + lane + 32);
        a0.x += v0.x; a0.y += v0.y; a0.z += v0.z; a0.w += v0.w;
        a1.x += v1.x; a1.y += v1.y; a1.z += v1.z; a1.w += v1.w;
    }
    float binv = deg > 0 ? 1.f / (float)deg : 0.f;
    a0.x *= binv; a0.y *= binv; a0.z *= binv; a0.w *= binv;
    a1.x *= binv; a1.y *= binv; a1.z *= binv; a1.w *= binv;
    float4* mr = (float4*)(g_m + (size_t)w * F_DIM);
    mr[lane]      = a0;
    mr[lane + 32] = a1;
}

__device__ __forceinline__ float prelu(float v, float a) {
    return v >= 0.f ? v : a * v;
}

// ------- gather hyperedge -> node, fused epilogue
__global__ __launch_bounds__(256)
void k_gather_e2n(float* __restrict__ dout, const float* __restrict__ bias,
                  const float* __restrict__ aP, const float* __restrict__ xres,
                  int use_out, int addres) {
    int w = (blockIdx.x * blockDim.x + threadIdx.x) >> 5;
    if (w >= N_NODES) return;
    int lane = threadIdx.x & 31;
    int off = g_offD[w];
    int deg = g_degD[w];
    const int* __restrict__ adj = g_adjD + off;

    float4 a0 = make_float4(0.f, 0.f, 0.f, 0.f);
    float4 a1 = make_float4(0.f, 0.f, 0.f, 0.f);
    #pragma unroll 4
    for (int j = 0; j < deg; ++j) {
        int e = __ldg(adj + j);
        const float4* r = (const float4*)(g_m + (size_t)e * F_DIM);
        float4 v0 = __ldg(r + lane);
        float4 v1 = __ldg(r + lane + 32);
        a0.x += v0.x; a0.y += v0.y; a0.z += v0.z; a0.w += v0.w;
        a1.x += v1.x; a1.y += v1.y; a1.z += v1.z; a1.w += v1.w;
    }
    float dinv = deg > 0 ? 1.f / (float)deg : 0.f;
    float av = __ldg(aP);
    float4 bb0 = *(const float4*)(bias + lane * 4);
    float4 bb1 = *(const float4*)(bias + 128 + lane * 4);

    float4 r0, r1;
    r0.x = fmaf(a0.x, dinv, bb0.x); r0.y = fmaf(a0.y, dinv, bb0.y);
    r0.z = fmaf(a0.z, dinv, bb0.z); r0.w = fmaf(a0.w, dinv, bb0.w);
    r1.x = fmaf(a1.x, dinv, bb1.x); r1.y = fmaf(a1.y, dinv, bb1.y);
    r1.z = fmaf(a1.z, dinv, bb1.z); r1.w = fmaf(a1.w, dinv, bb1.w);

    if (addres) {
        const float4* xr = (const float4*)(xres + (size_t)w * F_DIM);
        float4 x0 = __ldg(xr + lane), x1 = __ldg(xr + lane + 32);
        r0.x += x0.x; r0.y += x0.y; r0.z += x0.z; r0.w += x0.w;
        r1.x += x1.x; r1.y += x1.y; r1.z += x1.z; r1.w += x1.w;
    }

    r0.x = prelu(r0.x, av); r0.y = prelu(r0.y, av);
    r0.z = prelu(r0.z, av); r0.w = prelu(r0.w, av);
    r1.x = prelu(r1.x, av); r1.y = prelu(r1.y, av);
    r1.z = prelu(r1.z, av); r1.w = prelu(r1.w, av);

    float* dstp = use_out ? dout : g_h;   // device-side select
    float4* dr = (float4*)(dstp + (size_t)w * F_DIM);
    dr[lane]      = r0;
    dr[lane + 32] = r1;
}

// ---------------- launch ----------------
extern "C" void kernel_launch(void* const* d_in, const int* in_sizes, int n_in,
                              void* d_out, int out_size) {
    const float* x  = (const float*)d_in[0];
    const int*   ei = (const int*)  d_in[1];
    const float* W1 = (const float*)d_in[2];
    const float* b1 = (const float*)d_in[3];
    const float* W2 = (const float*)d_in[4];
    const float* b2 = (const float*)d_in[5];
    const float* a  = (const float*)d_in[6];
    float* out = (float*)d_out;

    dim3 ggrid(F_DIM / GBN, (N_NODES + GBM - 1) / GBM);
    const int GAT = (N_NODES * 32 + 255) / 256;   // warp per node

    // ---- CSR build (shared by both layers) ----
    k_zero_counts<<<(N_NODES + 255) / 256, 256>>>();
    k_count<<<(NNZ + 255) / 256, 256>>>(ei);
    k_scan1<<<dim3(NB1, 2), 1024>>>();
    k_scan2<<<dim3(1, 2), 128>>>();
    k_scan3<<<dim3(NB1, 2), 1024>>>();
    k_fill<<<(NNZ + 255) / 256, 256>>>(ei);

    // ---- layer 1 ----
    k_gemm<<<ggrid, 256>>>(x, W1, 0);
    k_gather_n2e<<<GAT, 256>>>();
    k_gather_e2n<<<GAT, 256>>>(out, b1, a, x, 0, 0);

    // ---- layer 2 ----
    k_gemm<<<ggrid, 256>>>(x /*unused*/, W2, 1);
    k_gather_n2e<<<GAT, 256>>>();
    k_gather_e2n<<<GAT, 256>>>(out, b2, a, x, 1, 1);
}

// round 6
// speedup vs baseline: 1.6829x; 1.6829x over previous
#include <cuda_runtime.h>
#include <cuda_fp16.h>
#include <cstddef>
#include <cstdint>

#define N_NODES 100000
#define F_DIM   256
#define NNZ     1600000
#define NB1     98          // ceil(N_NODES/1024)

// ---------------- scratch (no allocation allowed) ----------------
// __device__ symbols are ONLY referenced from device code, never passed
// as kernel arguments from host.
__device__ float g_xt[(size_t)N_NODES * F_DIM];  // GEMM output (both layers)
__device__ float g_m [(size_t)N_NODES * F_DIM];  // hyperedge accumulator
__device__ float g_h [(size_t)N_NODES * F_DIM];  // layer-1 hidden

__device__ __half g_W1hi[F_DIM * F_DIM];  // W1^T hi  [n][k]
__device__ __half g_W1lo[F_DIM * F_DIM];  // W1^T lo  [n][k]
__device__ __half g_W2hi[F_DIM * F_DIM];  // W2^T hi  [n][k]
__device__ __half g_W2lo[F_DIM * F_DIM];  // W2^T lo  [n][k]

__device__ int g_degD[N_NODES];
__device__ int g_degB[N_NODES];
__device__ int g_offD[N_NODES];
__device__ int g_offB[N_NODES];
__device__ int g_curD[N_NODES];
__device__ int g_curB[N_NODES];
__device__ int g_adjD[NNZ];       // grouped by src: stores dst ids
__device__ int g_adjB[NNZ];       // grouped by dst: stores src ids
__device__ int g_bsumD[NB1];
__device__ int g_bsumB[NB1];

// ---------------- CSR build ----------------
__global__ void k_zero_counts() {
    int i = blockIdx.x * blockDim.x + threadIdx.x;
    if (i < N_NODES) { g_degD[i] = 0; g_degB[i] = 0; }
}

__global__ void k_count(const int* __restrict__ ei) {
    int i = blockIdx.x * blockDim.x + threadIdx.x;
    if (i < NNZ) {
        atomicAdd(&g_degD[ei[i]], 1);
        atomicAdd(&g_degB[ei[i + NNZ]], 1);
    }
}

__global__ void k_scan1() {
    int which = blockIdx.y;
    const int* __restrict__ in  = which ? g_degB  : g_degD;
    int* __restrict__ out       = which ? g_offB  : g_offD;
    int* __restrict__ bsums     = which ? g_bsumB : g_bsumD;
    __shared__ int sh[1024];
    int g = blockIdx.x * 1024 + threadIdx.x;
    int v = (g < N_NODES) ? in[g] : 0;
    sh[threadIdx.x] = v;
    __syncthreads();
    #pragma unroll
    for (int off = 1; off < 1024; off <<= 1) {
        int t = (threadIdx.x >= off) ? sh[threadIdx.x - off] : 0;
        __syncthreads();
        sh[threadIdx.x] += t;
        __syncthreads();
    }
    if (g < N_NODES) out[g] = sh[threadIdx.x] - v;   // exclusive
    if (threadIdx.x == 1023) bsums[blockIdx.x] = sh[1023];
}

__global__ void k_scan2() {
    int* __restrict__ bsums = blockIdx.y ? g_bsumB : g_bsumD;
    __shared__ int sh[128];
    int v = (threadIdx.x < NB1) ? bsums[threadIdx.x] : 0;
    sh[threadIdx.x] = v;
    __syncthreads();
    #pragma unroll
    for (int off = 1; off < 128; off <<= 1) {
        int t = (threadIdx.x >= off) ? sh[threadIdx.x - off] : 0;
        __syncthreads();
        sh[threadIdx.x] += t;
        __syncthreads();
    }
    if (threadIdx.x < NB1) bsums[threadIdx.x] = sh[threadIdx.x] - v;
}

__global__ void k_scan3() {
    int which = blockIdx.y;
    int* __restrict__ out         = which ? g_offB  : g_offD;
    const int* __restrict__ bsums = which ? g_bsumB : g_bsumD;
    int* __restrict__ cur         = which ? g_curB  : g_curD;
    int g = blockIdx.x * 1024 + threadIdx.x;
    if (g < N_NODES) {
        int v = out[g] + bsums[blockIdx.x];
        out[g] = v;
        cur[g] = v;
    }
}

__global__ void k_fill(const int* __restrict__ ei) {
    int i = blockIdx.x * blockDim.x + threadIdx.x;
    if (i < NNZ) {
        int s = ei[i], d = ei[i + NNZ];
        g_adjD[atomicAdd(&g_curD[s], 1)] = d;
        g_adjB[atomicAdd(&g_curB[d], 1)] = s;
    }
}

// ---------------- W prep: transpose + hi/lo f16 split ----------------
// Whi[n][k] + Wlo[n][k] = W[k][n]; which: 0 -> W1 bufs, 1 -> W2 bufs
__global__ void k_prep_w(const float* __restrict__ W, int which) {
    int i = blockIdx.x * blockDim.x + threadIdx.x;   // 65536 threads total
    int k = i >> 8;
    int n = i & 255;
    float w = W[k * F_DIM + n];                      // coalesced in n
    __half hi = __float2half_rn(w);
    __half lo = __float2half_rn(w - __half2float(hi));
    __half* dh = which ? g_W2hi : g_W1hi;
    __half* dl = which ? g_W2lo : g_W1lo;
    dh[n * F_DIM + k] = hi;
    dl[n * F_DIM + k] = lo;
}

// ---------------- HMMA GEMM via mma.sync (portable, no 'a' suffix) -------
// g_xt[M,256] = A[M,256] @ W[256,256], fp32 via f16 hi/lo 3-pass split.
// CTA: 256 threads (8 warps as 4m x 2n), tile 128x128, K chunk 32.
#define KCH 32
#define LDA 40                        // padded row stride (halves)

__device__ __forceinline__ uint32_t smem_u32(const void* p) {
    uint32_t a;
    asm("{ .reg .u64 t; cvta.to.shared.u64 t, %1; cvt.u32.u64 %0, t; }"
        : "=r"(a) : "l"(p));
    return a;
}
__device__ __forceinline__ void ldsm4(uint32_t& r0, uint32_t& r1,
                                      uint32_t& r2, uint32_t& r3, uint32_t a) {
    asm volatile("ldmatrix.sync.aligned.m8n8.x4.shared.b16 {%0,%1,%2,%3}, [%4];"
                 : "=r"(r0), "=r"(r1), "=r"(r2), "=r"(r3) : "r"(a));
}
__device__ __forceinline__ void mma16816(float* d, const uint32_t* a,
                                         const uint32_t* b) {
    asm volatile(
        "mma.sync.aligned.m16n8k16.row.col.f32.f16.f16.f32 "
        "{%0,%1,%2,%3},{%4,%5,%6,%7},{%8,%9},{%0,%1,%2,%3};"
        : "+f"(d[0]), "+f"(d[1]), "+f"(d[2]), "+f"(d[3])
        : "r"(a[0]), "r"(a[1]), "r"(a[2]), "r"(a[3]), "r"(b[0]), "r"(b[1]));
}

__global__ __launch_bounds__(256, 2)
void k_gemm_mma(const float* __restrict__ A_ext, int use_h, int use_w2) {
    __shared__ __half As_hi[128 * LDA];
    __shared__ __half As_lo[128 * LDA];
    __shared__ __half Bs_hi[128 * LDA];
    __shared__ __half Bs_lo[128 * LDA];

    const float*  __restrict__ A  = use_h  ? g_h    : A_ext;   // device-side
    const __half* __restrict__ Wh = use_w2 ? g_W2hi : g_W1hi;
    const __half* __restrict__ Wl = use_w2 ? g_W2lo : g_W1lo;

    int tid  = threadIdx.x;
    int wid  = tid >> 5;
    int lane = tid & 31;
    int wm   = wid & 3;        // warp m index (4) -> rows wm*32
    int wn   = wid >> 2;       // warp n index (2) -> cols wn*64
    int bm   = blockIdx.y * 128;
    int bn   = blockIdx.x * 128;

    uint32_t sAhi = smem_u32(As_hi), sAlo = smem_u32(As_lo);
    uint32_t sBhi = smem_u32(Bs_hi), sBlo = smem_u32(Bs_lo);

    float acc[2][8][4];
    #pragma unroll
    for (int i = 0; i < 2; ++i)
        #pragma unroll
        for (int j = 0; j < 8; ++j)
            #pragma unroll
            for (int c = 0; c < 4; ++c) acc[i][j][c] = 0.f;

    int lanerow = lane & 15;
    int lanek   = (lane >> 4) << 3;   // 0 or 8

    for (int k0 = 0; k0 < F_DIM; k0 += KCH) {
        // ---- A: 128 rows x 32 fp32 -> hi/lo f16 smem ----
        #pragma unroll
        for (int l = 0; l < 4; ++l) {
            int idx = tid + l * 256;       // 0..1023
            int m = idx >> 3;              // 0..127
            int j = idx & 7;               // float4 idx -> klocal j*4
            int grow = bm + m;
            float4 v = make_float4(0.f, 0.f, 0.f, 0.f);
            if (grow < N_NODES)
                v = *(const float4*)(A + (size_t)grow * F_DIM + k0 + j * 4);
            __half h0 = __float2half_rn(v.x), h1 = __float2half_rn(v.y);
            __half h2 = __float2half_rn(v.z), h3 = __float2half_rn(v.w);
            __half l0 = __float2half_rn(v.x - __half2float(h0));
            __half l1 = __float2half_rn(v.y - __half2float(h1));
            __half l2 = __float2half_rn(v.z - __half2float(h2));
            __half l3 = __float2half_rn(v.w - __half2float(h3));
            int o = m * LDA + j * 4;
            *(__half2*)&As_hi[o]     = __halves2half2(h0, h1);
            *(__half2*)&As_hi[o + 2] = __halves2half2(h2, h3);
            *(__half2*)&As_lo[o]     = __halves2half2(l0, l1);
            *(__half2*)&As_lo[o + 2] = __halves2half2(l2, l3);
        }
        // ---- B: 128 n-rows x 32 k halves from Whi/Wlo [n][k] ----
        #pragma unroll
        for (int l = 0; l < 2; ++l) {
            int idx = tid + l * 256;       // 0..511
            int n = idx >> 2;              // 0..127
            int j = idx & 3;               // uint4 idx -> klocal j*8
            size_t gsrc = (size_t)(bn + n) * F_DIM + k0 + j * 8;
            int o = n * LDA + j * 8;
            *(uint4*)&Bs_hi[o] = *(const uint4*)(Wh + gsrc);
            *(uint4*)&Bs_lo[o] = *(const uint4*)(Wl + gsrc);
        }
        __syncthreads();

        #pragma unroll
        for (int ks = 0; ks < KCH; ks += 16) {
            uint32_t ahi[2][4], alo[2][4];
            #pragma unroll
            for (int mf = 0; mf < 2; ++mf) {
                uint32_t off = (uint32_t)((wm * 32 + mf * 16 + lanerow) * LDA
                                          + ks + lanek) * 2;
                ldsm4(ahi[mf][0], ahi[mf][1], ahi[mf][2], ahi[mf][3], sAhi + off);
                ldsm4(alo[mf][0], alo[mf][1], alo[mf][2], alo[mf][3], sAlo + off);
            }
            #pragma unroll
            for (int h = 0; h < 2; ++h) {      // two halves of 4 n-tiles
                uint32_t bh[4][2], bl[4][2];
                #pragma unroll
                for (int g = 0; g < 2; ++g) {  // each x4 covers 2 n-tiles
                    uint32_t off = (uint32_t)((wn * 64 + (h * 2 + g) * 16
                                               + lanerow) * LDA + ks + lanek) * 2;
                    uint32_t r0, r1, r2, r3;
                    ldsm4(r0, r1, r2, r3, sBhi + off);
                    bh[g * 2][0] = r0; bh[g * 2][1] = r2;
                    bh[g * 2 + 1][0] = r1; bh[g * 2 + 1][1] = r3;
                    ldsm4(r0, r1, r2, r3, sBlo + off);
                    bl[g * 2][0] = r0; bl[g * 2][1] = r2;
                    bl[g * 2 + 1][0] = r1; bl[g * 2 + 1][1] = r3;
                }
                #pragma unroll
                for (int mf = 0; mf < 2; ++mf)
                    #pragma unroll
                    for (int t = 0; t < 4; ++t) {
                        float* d = acc[mf][h * 4 + t];
                        mma16816(d, ahi[mf], bh[t]);   // hi*hi
                        mma16816(d, alo[mf], bh[t]);   // lo*hi
                        mma16816(d, ahi[mf], bl[t]);   // hi*lo
                    }
            }
        }
        __syncthreads();
    }

    // ---- epilogue ----
    int qrow = lane >> 2;          // 0..7
    int qcol = (lane & 3) * 2;     // 0,2,4,6
    #pragma unroll
    for (int mf = 0; mf < 2; ++mf) {
        int r0 = bm + wm * 32 + mf * 16 + qrow;
        #pragma unroll
        for (int nt = 0; nt < 8; ++nt) {
            int col = bn + wn * 64 + nt * 8 + qcol;
            float* d = acc[mf][nt];
            if (r0 < N_NODES)
                *(float2*)(g_xt + (size_t)r0 * F_DIM + col) = make_float2(d[0], d[1]);
            if (r0 + 8 < N_NODES)
                *(float2*)(g_xt + (size_t)(r0 + 8) * F_DIM + col) = make_float2(d[2], d[3]);
        }
    }
}

// ------- gather node -> hyperedge: g_m[e] = Binv[e] * sum_{src in e} g_xt[src]
__global__ __launch_bounds__(256)
void k_gather_n2e() {
    int w = (blockIdx.x * blockDim.x + threadIdx.x) >> 5;
    if (w >= N_NODES) return;
    int lane = threadIdx.x & 31;
    int off = g_offB[w];
    int deg = g_degB[w];
    const int* __restrict__ adj = g_adjB + off;

    float4 a0 = make_float4(0.f, 0.f, 0.f, 0.f);
    float4 a1 = make_float4(0.f, 0.f, 0.f, 0.f);
    #pragma unroll 4
    for (int j = 0; j < deg; ++j) {
        int s = __ldg(adj + j);
        const float4* r = (const float4*)(g_xt + (size_t)s * F_DIM);
        float4 v0 = __ldg(r + lane);
        float4 v1 = __ldg(r + lane + 32);
        a0.x += v0.x; a0.y += v0.y; a0.z += v0.z; a0.w += v0.w;
        a1.x += v1.x; a1.y += v1.y; a1.z += v1.z; a1.w += v1.w;
    }
    float binv = deg > 0 ? 1.f / (float)deg : 0.f;
    a0.x *= binv; a0.y *= binv; a0.z *= binv; a0.w *= binv;
    a1.x *= binv; a1.y *= binv; a1.z *= binv; a1.w *= binv;
    float4* mr = (float4*)(g_m + (size_t)w * F_DIM);
    mr[lane]      = a0;
    mr[lane + 32] = a1;
}

__device__ __forceinline__ float prelu(float v, float a) {
    return v >= 0.f ? v : a * v;
}

// ------- gather hyperedge -> node, fused epilogue
__global__ __launch_bounds__(256)
void k_gather_e2n(float* __restrict__ dout, const float* __restrict__ bias,
                  const float* __restrict__ aP, const float* __restrict__ xres,
                  int use_out, int addres) {
    int w = (blockIdx.x * blockDim.x + threadIdx.x) >> 5;
    if (w >= N_NODES) return;
    int lane = threadIdx.x & 31;
    int off = g_offD[w];
    int deg = g_degD[w];
    const int* __restrict__ adj = g_adjD + off;

    float4 a0 = make_float4(0.f, 0.f, 0.f, 0.f);
    float4 a1 = make_float4(0.f, 0.f, 0.f, 0.f);
    #pragma unroll 4
    for (int j = 0; j < deg; ++j) {
        int e = __ldg(adj + j);
        const float4* r = (const float4*)(g_m + (size_t)e * F_DIM);
        float4 v0 = __ldg(r + lane);
        float4 v1 = __ldg(r + lane + 32);
        a0.x += v0.x; a0.y += v0.y; a0.z += v0.z; a0.w += v0.w;
        a1.x += v1.x; a1.y += v1.y; a1.z += v1.z; a1.w += v1.w;
    }
    float dinv = deg > 0 ? 1.f / (float)deg : 0.f;
    float av = __ldg(aP);
    float4 bb0 = *(const float4*)(bias + lane * 4);
    float4 bb1 = *(const float4*)(bias + 128 + lane * 4);

    float4 r0, r1;
    r0.x = fmaf(a0.x, dinv, bb0.x); r0.y = fmaf(a0.y, dinv, bb0.y);
    r0.z = fmaf(a0.z, dinv, bb0.z); r0.w = fmaf(a0.w, dinv, bb0.w);
    r1.x = fmaf(a1.x, dinv, bb1.x); r1.y = fmaf(a1.y, dinv, bb1.y);
    r1.z = fmaf(a1.z, dinv, bb1.z); r1.w = fmaf(a1.w, dinv, bb1.w);

    if (addres) {
        const float4* xr = (const float4*)(xres + (size_t)w * F_DIM);
        float4 x0 = __ldg(xr + lane), x1 = __ldg(xr + lane + 32);
        r0.x += x0.x; r0.y += x0.y; r0.z += x0.z; r0.w += x0.w;
        r1.x += x1.x; r1.y += x1.y; r1.z += x1.z; r1.w += x1.w;
    }

    r0.x = prelu(r0.x, av); r0.y = prelu(r0.y, av);
    r0.z = prelu(r0.z, av); r0.w = prelu(r0.w, av);
    r1.x = prelu(r1.x, av); r1.y = prelu(r1.y, av);
    r1.z = prelu(r1.z, av); r1.w = prelu(r1.w, av);

    float* dstp = use_out ? dout : g_h;   // device-side select
    float4* dr = (float4*)(dstp + (size_t)w * F_DIM);
    dr[lane]      = r0;
    dr[lane + 32] = r1;
}

// ---------------- launch ----------------
extern "C" void kernel_launch(void* const* d_in, const int* in_sizes, int n_in,
                              void* d_out, int out_size) {
    const float* x  = (const float*)d_in[0];
    const int*   ei = (const int*)  d_in[1];
    const float* W1 = (const float*)d_in[2];
    const float* b1 = (const float*)d_in[3];
    const float* W2 = (const float*)d_in[4];
    const float* b2 = (const float*)d_in[5];
    const float* a  = (const float*)d_in[6];
    float* out = (float*)d_out;

    const int GAT = (N_NODES * 32 + 255) / 256;   // warp per node
    dim3 ggrid(2, (N_NODES + 127) / 128);         // 2 n-tiles x 782 m-tiles

    // ---- CSR build + W prep (shared by both layers) ----
    k_zero_counts<<<(N_NODES + 255) / 256, 256>>>();
    k_count<<<(NNZ + 255) / 256, 256>>>(ei);
    k_scan1<<<dim3(NB1, 2), 1024>>>();
    k_scan2<<<dim3(1, 2), 128>>>();
    k_scan3<<<dim3(NB1, 2), 1024>>>();
    k_fill<<<(NNZ + 255) / 256, 256>>>(ei);
    k_prep_w<<<F_DIM * F_DIM / 256, 256>>>(W1, 0);
    k_prep_w<<<F_DIM * F_DIM / 256, 256>>>(W2, 1);

    // ---- layer 1 ----
    k_gemm_mma<<<ggrid, 256>>>(x, 0, 0);
    k_gather_n2e<<<GAT, 256>>>();
    k_gather_e2n<<<GAT, 256>>>(out, b1, a, x, 0, 0);

    // ---- layer 2 ----
    k_gemm_mma<<<ggrid, 256>>>(x /*unused*/, 1, 1);
    k_gather_n2e<<<GAT, 256>>>();
    k_gather_e2n<<<GAT, 256>>>(out, b2, a, x, 1, 1);
}

// round 7
// speedup vs baseline: 2.2398x; 1.3309x over previous
#include <cuda_runtime.h>
#include <cuda_fp16.h>
#include <cstddef>
#include <cstdint>

#define N_NODES 100000
#define F_DIM   256
#define NNZ     1600000
#define NB1     98          // ceil(N_NODES/1024)

// ---------------- scratch (no allocation allowed) ----------------
// __device__ symbols are ONLY referenced from device code, never passed
// as kernel arguments from host.
__device__ __half g_xt[(size_t)N_NODES * F_DIM];  // GEMM output, fp16 (gathered)
__device__ __half g_m [(size_t)N_NODES * F_DIM];  // hyperedge accum, fp16 (gathered)
__device__ float  g_h [(size_t)N_NODES * F_DIM];  // layer-1 hidden, fp32 (GEMM input)

__device__ __half g_W1hi[F_DIM * F_DIM];  // W1^T hi  [n][k]
__device__ __half g_W1lo[F_DIM * F_DIM];  // W1^T lo  [n][k]
__device__ __half g_W2hi[F_DIM * F_DIM];  // W2^T hi  [n][k]
__device__ __half g_W2lo[F_DIM * F_DIM];  // W2^T lo  [n][k]

__device__ int g_degD[N_NODES];
__device__ int g_degB[N_NODES];
__device__ int g_offD[N_NODES];
__device__ int g_offB[N_NODES];
__device__ int g_curD[N_NODES];
__device__ int g_curB[N_NODES];
__device__ int g_adjD[NNZ];       // grouped by src: stores dst ids
__device__ int g_adjB[NNZ];       // grouped by dst: stores src ids
__device__ int g_bsumD[NB1];
__device__ int g_bsumB[NB1];

// ---------------- CSR build ----------------
__global__ void k_zero_counts() {
    int i = blockIdx.x * blockDim.x + threadIdx.x;
    if (i < N_NODES) { g_degD[i] = 0; g_degB[i] = 0; }
}

__global__ void k_count(const int* __restrict__ ei) {
    int i = blockIdx.x * blockDim.x + threadIdx.x;
    if (i < NNZ) {
        atomicAdd(&g_degD[ei[i]], 1);
        atomicAdd(&g_degB[ei[i + NNZ]], 1);
    }
}

__global__ void k_scan1() {
    int which = blockIdx.y;
    const int* __restrict__ in  = which ? g_degB  : g_degD;
    int* __restrict__ out       = which ? g_offB  : g_offD;
    int* __restrict__ bsums     = which ? g_bsumB : g_bsumD;
    __shared__ int sh[1024];
    int g = blockIdx.x * 1024 + threadIdx.x;
    int v = (g < N_NODES) ? in[g] : 0;
    sh[threadIdx.x] = v;
    __syncthreads();
    #pragma unroll
    for (int off = 1; off < 1024; off <<= 1) {
        int t = (threadIdx.x >= off) ? sh[threadIdx.x - off] : 0;
        __syncthreads();
        sh[threadIdx.x] += t;
        __syncthreads();
    }
    if (g < N_NODES) out[g] = sh[threadIdx.x] - v;   // exclusive
    if (threadIdx.x == 1023) bsums[blockIdx.x] = sh[1023];
}

__global__ void k_scan2() {
    int* __restrict__ bsums = blockIdx.y ? g_bsumB : g_bsumD;
    __shared__ int sh[128];
    int v = (threadIdx.x < NB1) ? bsums[threadIdx.x] : 0;
    sh[threadIdx.x] = v;
    __syncthreads();
    #pragma unroll
    for (int off = 1; off < 128; off <<= 1) {
        int t = (threadIdx.x >= off) ? sh[threadIdx.x - off] : 0;
        __syncthreads();
        sh[threadIdx.x] += t;
        __syncthreads();
    }
    if (threadIdx.x < NB1) bsums[threadIdx.x] = sh[threadIdx.x] - v;
}

__global__ void k_scan3() {
    int which = blockIdx.y;
    int* __restrict__ out         = which ? g_offB  : g_offD;
    const int* __restrict__ bsums = which ? g_bsumB : g_bsumD;
    int* __restrict__ cur         = which ? g_curB  : g_curD;
    int g = blockIdx.x * 1024 + threadIdx.x;
    if (g < N_NODES) {
        int v = out[g] + bsums[blockIdx.x];
        out[g] = v;
        cur[g] = v;
    }
}

__global__ void k_fill(const int* __restrict__ ei) {
    int i = blockIdx.x * blockDim.x + threadIdx.x;
    if (i < NNZ) {
        int s = ei[i], d = ei[i + NNZ];
        g_adjD[atomicAdd(&g_curD[s], 1)] = d;
        g_adjB[atomicAdd(&g_curB[d], 1)] = s;
    }
}

// ---------------- W prep: transpose + hi/lo f16 split ----------------
// Whi[n][k] + Wlo[n][k] = W[k][n]; which: 0 -> W1 bufs, 1 -> W2 bufs
__global__ void k_prep_w(const float* __restrict__ W, int which) {
    int i = blockIdx.x * blockDim.x + threadIdx.x;   // 65536 threads total
    int k = i >> 8;
    int n = i & 255;
    float w = W[k * F_DIM + n];                      // coalesced in n
    __half hi = __float2half_rn(w);
    __half lo = __float2half_rn(w - __half2float(hi));
    __half* dh = which ? g_W2hi : g_W1hi;
    __half* dl = which ? g_W2lo : g_W1lo;
    dh[n * F_DIM + k] = hi;
    dl[n * F_DIM + k] = lo;
}

// ---------------- HMMA GEMM via mma.sync (portable, no 'a' suffix) -------
// g_xt[M,256](fp16) = A[M,256](fp32) @ W[256,256], via f16 hi/lo 3-pass split.
// CTA: 256 threads (8 warps as 4m x 2n), tile 128x128, K chunk 32.
#define KCH 32
#define LDA 40                        // padded row stride (halves)

__device__ __forceinline__ uint32_t smem_u32(const void* p) {
    uint32_t a;
    asm("{ .reg .u64 t; cvta.to.shared.u64 t, %1; cvt.u32.u64 %0, t; }"
        : "=r"(a) : "l"(p));
    return a;
}
__device__ __forceinline__ void ldsm4(uint32_t& r0, uint32_t& r1,
                                      uint32_t& r2, uint32_t& r3, uint32_t a) {
    asm volatile("ldmatrix.sync.aligned.m8n8.x4.shared.b16 {%0,%1,%2,%3}, [%4];"
                 : "=r"(r0), "=r"(r1), "=r"(r2), "=r"(r3) : "r"(a));
}
__device__ __forceinline__ void mma16816(float* d, const uint32_t* a,
                                         const uint32_t* b) {
    asm volatile(
        "mma.sync.aligned.m16n8k16.row.col.f32.f16.f16.f32 "
        "{%0,%1,%2,%3},{%4,%5,%6,%7},{%8,%9},{%0,%1,%2,%3};"
        : "+f"(d[0]), "+f"(d[1]), "+f"(d[2]), "+f"(d[3])
        : "r"(a[0]), "r"(a[1]), "r"(a[2]), "r"(a[3]), "r"(b[0]), "r"(b[1]));
}

__global__ __launch_bounds__(256, 2)
void k_gemm_mma(const float* __restrict__ A_ext, int use_h, int use_w2) {
    __shared__ __half As_hi[128 * LDA];
    __shared__ __half As_lo[128 * LDA];
    __shared__ __half Bs_hi[128 * LDA];
    __shared__ __half Bs_lo[128 * LDA];

    const float*  __restrict__ A  = use_h  ? g_h    : A_ext;   // device-side
    const __half* __restrict__ Wh = use_w2 ? g_W2hi : g_W1hi;
    const __half* __restrict__ Wl = use_w2 ? g_W2lo : g_W1lo;

    int tid  = threadIdx.x;
    int wid  = tid >> 5;
    int lane = tid & 31;
    int wm   = wid & 3;        // warp m index (4) -> rows wm*32
    int wn   = wid >> 2;       // warp n index (2) -> cols wn*64
    int bm   = blockIdx.y * 128;
    int bn   = blockIdx.x * 128;

    uint32_t sAhi = smem_u32(As_hi), sAlo = smem_u32(As_lo);
    uint32_t sBhi = smem_u32(Bs_hi), sBlo = smem_u32(Bs_lo);

    float acc[2][8][4];
    #pragma unroll
    for (int i = 0; i < 2; ++i)
        #pragma unroll
        for (int j = 0; j < 8; ++j)
            #pragma unroll
            for (int c = 0; c < 4; ++c) acc[i][j][c] = 0.f;

    int lanerow = lane & 15;
    int lanek   = (lane >> 4) << 3;   // 0 or 8

    for (int k0 = 0; k0 < F_DIM; k0 += KCH) {
        // ---- A: 128 rows x 32 fp32 -> hi/lo f16 smem ----
        #pragma unroll
        for (int l = 0; l < 4; ++l) {
            int idx = tid + l * 256;       // 0..1023
            int m = idx >> 3;              // 0..127
            int j = idx & 7;               // float4 idx -> klocal j*4
            int grow = bm + m;
            float4 v = make_float4(0.f, 0.f, 0.f, 0.f);
            if (grow < N_NODES)
                v = *(const float4*)(A + (size_t)grow * F_DIM + k0 + j * 4);
            __half h0 = __float2half_rn(v.x), h1 = __float2half_rn(v.y);
            __half h2 = __float2half_rn(v.z), h3 = __float2half_rn(v.w);
            __half l0 = __float2half_rn(v.x - __half2float(h0));
            __half l1 = __float2half_rn(v.y - __half2float(h1));
            __half l2 = __float2half_rn(v.z - __half2float(h2));
            __half l3 = __float2half_rn(v.w - __half2float(h3));
            int o = m * LDA + j * 4;
            *(__half2*)&As_hi[o]     = __halves2half2(h0, h1);
            *(__half2*)&As_hi[o + 2] = __halves2half2(h2, h3);
            *(__half2*)&As_lo[o]     = __halves2half2(l0, l1);
            *(__half2*)&As_lo[o + 2] = __halves2half2(l2, l3);
        }
        // ---- B: 128 n-rows x 32 k halves from Whi/Wlo [n][k] ----
        #pragma unroll
        for (int l = 0; l < 2; ++l) {
            int idx = tid + l * 256;       // 0..511
            int n = idx >> 2;              // 0..127
            int j = idx & 3;               // uint4 idx -> klocal j*8
            size_t gsrc = (size_t)(bn + n) * F_DIM + k0 + j * 8;
            int o = n * LDA + j * 8;
            *(uint4*)&Bs_hi[o] = *(const uint4*)(Wh + gsrc);
            *(uint4*)&Bs_lo[o] = *(const uint4*)(Wl + gsrc);
        }
        __syncthreads();

        #pragma unroll
        for (int ks = 0; ks < KCH; ks += 16) {
            uint32_t ahi[2][4], alo[2][4];
            #pragma unroll
            for (int mf = 0; mf < 2; ++mf) {
                uint32_t off = (uint32_t)((wm * 32 + mf * 16 + lanerow) * LDA
                                          + ks + lanek) * 2;
                ldsm4(ahi[mf][0], ahi[mf][1], ahi[mf][2], ahi[mf][3], sAhi + off);
                ldsm4(alo[mf][0], alo[mf][1], alo[mf][2], alo[mf][3], sAlo + off);
            }
            #pragma unroll
            for (int h = 0; h < 2; ++h) {      // two halves of 4 n-tiles
                uint32_t bh[4][2], bl[4][2];
                #pragma unroll
                for (int g = 0; g < 2; ++g) {  // each x4 covers 2 n-tiles
                    uint32_t off = (uint32_t)((wn * 64 + (h * 2 + g) * 16
                                               + lanerow) * LDA + ks + lanek) * 2;
                    uint32_t r0, r1, r2, r3;
                    ldsm4(r0, r1, r2, r3, sBhi + off);
                    bh[g * 2][0] = r0; bh[g * 2][1] = r2;
                    bh[g * 2 + 1][0] = r1; bh[g * 2 + 1][1] = r3;
                    ldsm4(r0, r1, r2, r3, sBlo + off);
                    bl[g * 2][0] = r0; bl[g * 2][1] = r2;
                    bl[g * 2 + 1][0] = r1; bl[g * 2 + 1][1] = r3;
                }
                #pragma unroll
                for (int mf = 0; mf < 2; ++mf)
                    #pragma unroll
                    for (int t = 0; t < 4; ++t) {
                        float* d = acc[mf][h * 4 + t];
                        mma16816(d, ahi[mf], bh[t]);   // hi*hi
                        mma16816(d, alo[mf], bh[t]);   // lo*hi
                        mma16816(d, ahi[mf], bl[t]);   // hi*lo
                    }
            }
        }
        __syncthreads();
    }

    // ---- epilogue: write fp16 g_xt ----
    int qrow = lane >> 2;          // 0..7
    int qcol = (lane & 3) * 2;     // 0,2,4,6
    #pragma unroll
    for (int mf = 0; mf < 2; ++mf) {
        int r0 = bm + wm * 32 + mf * 16 + qrow;
        #pragma unroll
        for (int nt = 0; nt < 8; ++nt) {
            int col = bn + wn * 64 + nt * 8 + qcol;
            float* d = acc[mf][nt];
            if (r0 < N_NODES)
                *(__half2*)(g_xt + (size_t)r0 * F_DIM + col) =
                    __floats2half2_rn(d[0], d[1]);
            if (r0 + 8 < N_NODES)
                *(__half2*)(g_xt + (size_t)(r0 + 8) * F_DIM + col) =
                    __floats2half2_rn(d[2], d[3]);
        }
    }
}

// ---------------- fp16 row helpers ----------------
// One uint4 = 8 halves. Row = 256 halves = 32 lanes x 1 uint4.
__device__ __forceinline__ void acc8_from_u4(float* acc, uint4 v) {
    __half2* h = (__half2*)&v;
    #pragma unroll
    for (int i = 0; i < 4; ++i) {
        float2 f = __half22float2(h[i]);
        acc[2 * i]     += f.x;
        acc[2 * i + 1] += f.y;
    }
}
__device__ __forceinline__ uint4 u4_from_8f(const float* s) {
    uint4 v;
    __half2* h = (__half2*)&v;
    #pragma unroll
    for (int i = 0; i < 4; ++i)
        h[i] = __floats2half2_rn(s[2 * i], s[2 * i + 1]);
    return v;
}

// ------- gather node -> hyperedge: g_m[e] = Binv[e] * sum_{src in e} g_xt[src]
__global__ __launch_bounds__(256)
void k_gather_n2e() {
    int w = (blockIdx.x * blockDim.x + threadIdx.x) >> 5;
    if (w >= N_NODES) return;
    int lane = threadIdx.x & 31;
    int off = g_offB[w];
    int deg = g_degB[w];
    const int* __restrict__ adj = g_adjB + off;

    float acc[8] = {0.f, 0.f, 0.f, 0.f, 0.f, 0.f, 0.f, 0.f};
    #pragma unroll 4
    for (int j = 0; j < deg; ++j) {
        int s = __ldg(adj + j);
        uint4 v = __ldg((const uint4*)(g_xt + (size_t)s * F_DIM) + lane);
        acc8_from_u4(acc, v);
    }
    float binv = deg > 0 ? 1.f / (float)deg : 0.f;
    #pragma unroll
    for (int i = 0; i < 8; ++i) acc[i] *= binv;
    *((uint4*)(g_m + (size_t)w * F_DIM) + lane) = u4_from_8f(acc);
}

__device__ __forceinline__ float prelu(float v, float a) {
    return v >= 0.f ? v : a * v;
}

// ------- gather hyperedge -> node, fused epilogue (fp32 output)
__global__ __launch_bounds__(256)
void k_gather_e2n(float* __restrict__ dout, const float* __restrict__ bias,
                  const float* __restrict__ aP, const float* __restrict__ xres,
                  int use_out, int addres) {
    int w = (blockIdx.x * blockDim.x + threadIdx.x) >> 5;
    if (w >= N_NODES) return;
    int lane = threadIdx.x & 31;
    int off = g_offD[w];
    int deg = g_degD[w];
    const int* __restrict__ adj = g_adjD + off;

    float acc[8] = {0.f, 0.f, 0.f, 0.f, 0.f, 0.f, 0.f, 0.f};
    #pragma unroll 4
    for (int j = 0; j < deg; ++j) {
        int e = __ldg(adj + j);
        uint4 v = __ldg((const uint4*)(g_m + (size_t)e * F_DIM) + lane);
        acc8_from_u4(acc, v);
    }
    float dinv = deg > 0 ? 1.f / (float)deg : 0.f;
    float av = __ldg(aP);
    float4 bb0 = *(const float4*)(bias + lane * 8);
    float4 bb1 = *(const float4*)(bias + lane * 8 + 4);
    float r[8];
    r[0] = fmaf(acc[0], dinv, bb0.x); r[1] = fmaf(acc[1], dinv, bb0.y);
    r[2] = fmaf(acc[2], dinv, bb0.z); r[3] = fmaf(acc[3], dinv, bb0.w);
    r[4] = fmaf(acc[4], dinv, bb1.x); r[5] = fmaf(acc[5], dinv, bb1.y);
    r[6] = fmaf(acc[6], dinv, bb1.z); r[7] = fmaf(acc[7], dinv, bb1.w);

    if (addres) {
        const float* xr = xres + (size_t)w * F_DIM + lane * 8;
        float4 x0 = __ldg((const float4*)xr);
        float4 x1 = __ldg((const float4*)(xr + 4));
        r[0] += x0.x; r[1] += x0.y; r[2] += x0.z; r[3] += x0.w;
        r[4] += x1.x; r[5] += x1.y; r[6] += x1.z; r[7] += x1.w;
    }
    #pragma unroll
    for (int i = 0; i < 8; ++i) r[i] = prelu(r[i], av);

    float* dstp = use_out ? dout : g_h;   // device-side select
    float* dr = dstp + (size_t)w * F_DIM + lane * 8;
    *(float4*)dr       = make_float4(r[0], r[1], r[2], r[3]);
    *(float4*)(dr + 4) = make_float4(r[4], r[5], r[6], r[7]);
}

// ---------------- launch ----------------
extern "C" void kernel_launch(void* const* d_in, const int* in_sizes, int n_in,
                              void* d_out, int out_size) {
    const float* x  = (const float*)d_in[0];
    const int*   ei = (const int*)  d_in[1];
    const float* W1 = (const float*)d_in[2];
    const float* b1 = (const float*)d_in[3];
    const float* W2 = (const float*)d_in[4];
    const float* b2 = (const float*)d_in[5];
    const float* a  = (const float*)d_in[6];
    float* out = (float*)d_out;

    const int GAT = (N_NODES * 32 + 255) / 256;   // warp per node
    dim3 ggrid(2, (N_NODES + 127) / 128);         // 2 n-tiles x 782 m-tiles

    // ---- CSR build + W prep (shared by both layers) ----
    k_zero_counts<<<(N_NODES + 255) / 256, 256>>>();
    k_count<<<(NNZ + 255) / 256, 256>>>(ei);
    k_scan1<<<dim3(NB1, 2), 1024>>>();
    k_scan2<<<dim3(1, 2), 128>>>();
    k_scan3<<<dim3(NB1, 2), 1024>>>();
    k_fill<<<(NNZ + 255) / 256, 256>>>(ei);
    k_prep_w<<<F_DIM * F_DIM / 256, 256>>>(W1, 0);
    k_prep_w<<<F_DIM * F_DIM / 256, 256>>>(W2, 1);

    // ---- layer 1 ----
    k_gemm_mma<<<ggrid, 256>>>(x, 0, 0);
    k_gather_n2e<<<GAT, 256>>>();
    k_gather_e2n<<<GAT, 256>>>(out, b1, a, x, 0, 0);

    // ---- layer 2 ----
    k_gemm_mma<<<ggrid, 256>>>(x /*unused*/, 1, 1);
    k_gather_n2e<<<GAT, 256>>>();
    k_gather_e2n<<<GAT, 256>>>(out, b2, a, x, 1, 1);
}

// round 8
// speedup vs baseline: 2.7285x; 1.2182x over previous
#include <cuda_runtime.h>
#include <cuda_fp16.h>
#include <cstddef>
#include <cstdint>

#define N_NODES 100000
#define F_DIM   256
#define NNZ     1600000
#define NB1     98          // ceil(N_NODES/1024)

// ---------------- scratch (no allocation allowed) ----------------
// __device__ symbols are ONLY referenced from device code, never passed
// as kernel arguments from host.
__device__ __half g_xt[(size_t)N_NODES * F_DIM];  // GEMM output, fp16 (gathered)
__device__ __half g_m [(size_t)N_NODES * F_DIM];  // hyperedge accum, fp16 (gathered)
__device__ __half g_h [(size_t)N_NODES * F_DIM];  // layer-1 hidden, fp16

__device__ __half g_W1h[F_DIM * F_DIM];  // W1^T f16  [n][k]
__device__ __half g_W2h[F_DIM * F_DIM];  // W2^T f16  [n][k]

__device__ int g_degD[N_NODES];
__device__ int g_degB[N_NODES];
__device__ int g_offD[N_NODES];
__device__ int g_offB[N_NODES];
__device__ int g_curD[N_NODES];
__device__ int g_curB[N_NODES];
__device__ int g_adjD[NNZ];       // grouped by src: stores dst ids
__device__ int g_adjB[NNZ];       // grouped by dst: stores src ids
__device__ int g_bsumD[NB1];
__device__ int g_bsumB[NB1];

// ---------------- CSR build ----------------
__global__ void k_zero_counts() {
    int i = blockIdx.x * blockDim.x + threadIdx.x;
    if (i < N_NODES) { g_degD[i] = 0; g_degB[i] = 0; }
}

__global__ void k_count(const int* __restrict__ ei) {
    int i = blockIdx.x * blockDim.x + threadIdx.x;
    if (i < NNZ) {
        atomicAdd(&g_degD[ei[i]], 1);
        atomicAdd(&g_degB[ei[i + NNZ]], 1);
    }
}

__global__ void k_scan1() {
    int which = blockIdx.y;
    const int* __restrict__ in  = which ? g_degB  : g_degD;
    int* __restrict__ out       = which ? g_offB  : g_offD;
    int* __restrict__ bsums     = which ? g_bsumB : g_bsumD;
    __shared__ int sh[1024];
    int g = blockIdx.x * 1024 + threadIdx.x;
    int v = (g < N_NODES) ? in[g] : 0;
    sh[threadIdx.x] = v;
    __syncthreads();
    #pragma unroll
    for (int off = 1; off < 1024; off <<= 1) {
        int t = (threadIdx.x >= off) ? sh[threadIdx.x - off] : 0;
        __syncthreads();
        sh[threadIdx.x] += t;
        __syncthreads();
    }
    if (g < N_NODES) out[g] = sh[threadIdx.x] - v;   // exclusive
    if (threadIdx.x == 1023) bsums[blockIdx.x] = sh[1023];
}

__global__ void k_scan2() {
    int* __restrict__ bsums = blockIdx.y ? g_bsumB : g_bsumD;
    __shared__ int sh[128];
    int v = (threadIdx.x < NB1) ? bsums[threadIdx.x] : 0;
    sh[threadIdx.x] = v;
    __syncthreads();
    #pragma unroll
    for (int off = 1; off < 128; off <<= 1) {
        int t = (threadIdx.x >= off) ? sh[threadIdx.x - off] : 0;
        __syncthreads();
        sh[threadIdx.x] += t;
        __syncthreads();
    }
    if (threadIdx.x < NB1) bsums[threadIdx.x] = sh[threadIdx.x] - v;
}

__global__ void k_scan3() {
    int which = blockIdx.y;
    int* __restrict__ out         = which ? g_offB  : g_offD;
    const int* __restrict__ bsums = which ? g_bsumB : g_bsumD;
    int* __restrict__ cur         = which ? g_curB  : g_curD;
    int g = blockIdx.x * 1024 + threadIdx.x;
    if (g < N_NODES) {
        int v = out[g] + bsums[blockIdx.x];
        out[g] = v;
        cur[g] = v;
    }
}

__global__ void k_fill(const int* __restrict__ ei) {
    int i = blockIdx.x * blockDim.x + threadIdx.x;
    if (i < NNZ) {
        int s = ei[i], d = ei[i + NNZ];
        g_adjD[atomicAdd(&g_curD[s], 1)] = d;
        g_adjB[atomicAdd(&g_curB[d], 1)] = s;
    }
}

// ---------------- W prep: transpose + f16 ----------------
// Wh[n][k] = f16(W[k][n]); which: 0 -> W1, 1 -> W2
__global__ void k_prep_w(const float* __restrict__ W, int which) {
    int i = blockIdx.x * blockDim.x + threadIdx.x;   // 65536 threads total
    int k = i >> 8;
    int n = i & 255;
    float w = W[k * F_DIM + n];                      // coalesced in n
    __half* dh = which ? g_W2h : g_W1h;
    dh[n * F_DIM + k] = __float2half_rn(w);
}

// ---------------- HMMA GEMM via mma.sync (portable) ----------------
// g_xt[M,256](fp16) = A[M,256] @ W[256,256], single-pass f16, fp32 accum.
// CTA: 256 threads (8 warps as 4m x 2n), tile 128x128, K chunk 32.
#define KCH 32
#define LDA 40                        // padded row stride (halves)

__device__ __forceinline__ uint32_t smem_u32(const void* p) {
    uint32_t a;
    asm("{ .reg .u64 t; cvta.to.shared.u64 t, %1; cvt.u32.u64 %0, t; }"
        : "=r"(a) : "l"(p));
    return a;
}
__device__ __forceinline__ void ldsm4(uint32_t& r0, uint32_t& r1,
                                      uint32_t& r2, uint32_t& r3, uint32_t a) {
    asm volatile("ldmatrix.sync.aligned.m8n8.x4.shared.b16 {%0,%1,%2,%3}, [%4];"
                 : "=r"(r0), "=r"(r1), "=r"(r2), "=r"(r3) : "r"(a));
}
__device__ __forceinline__ void mma16816(float* d, const uint32_t* a,
                                         const uint32_t* b) {
    asm volatile(
        "mma.sync.aligned.m16n8k16.row.col.f32.f16.f16.f32 "
        "{%0,%1,%2,%3},{%4,%5,%6,%7},{%8,%9},{%0,%1,%2,%3};"
        : "+f"(d[0]), "+f"(d[1]), "+f"(d[2]), "+f"(d[3])
        : "r"(a[0]), "r"(a[1]), "r"(a[2]), "r"(a[3]), "r"(b[0]), "r"(b[1]));
}

__global__ __launch_bounds__(256, 2)
void k_gemm_mma(const float* __restrict__ A_ext, int use_h, int use_w2) {
    __shared__ __half As[128 * LDA];
    __shared__ __half Bs[128 * LDA];

    const __half* __restrict__ Wh = use_w2 ? g_W2h : g_W1h;

    int tid  = threadIdx.x;
    int wid  = tid >> 5;
    int lane = tid & 31;
    int wm   = wid & 3;        // warp m index (4) -> rows wm*32
    int wn   = wid >> 2;       // warp n index (2) -> cols wn*64
    int bm   = blockIdx.y * 128;
    int bn   = blockIdx.x * 128;

    uint32_t sA = smem_u32(As);
    uint32_t sB = smem_u32(Bs);

    float acc[2][8][4];
    #pragma unroll
    for (int i = 0; i < 2; ++i)
        #pragma unroll
        for (int j = 0; j < 8; ++j)
            #pragma unroll
            for (int c = 0; c < 4; ++c) acc[i][j][c] = 0.f;

    int lanerow = lane & 15;
    int lanek   = (lane >> 4) << 3;   // 0 or 8

    for (int k0 = 0; k0 < F_DIM; k0 += KCH) {
        // ---- A tile: 128 rows x 32 halves ----
        if (use_h) {
            // fp16 source: straight uint4 copy (8 halves per chunk)
            #pragma unroll
            for (int l = 0; l < 2; ++l) {
                int idx = tid + l * 256;   // 0..511
                int m = idx >> 2;          // 0..127
                int j = idx & 3;           // uint4 -> klocal j*8
                int grow = bm + m;
                uint4 v = make_uint4(0u, 0u, 0u, 0u);
                if (grow < N_NODES)
                    v = *(const uint4*)(g_h + (size_t)grow * F_DIM + k0 + j * 8);
                *(uint4*)&As[m * LDA + j * 8] = v;
            }
        } else {
            // fp32 source: convert on the fly
            #pragma unroll
            for (int l = 0; l < 4; ++l) {
                int idx = tid + l * 256;   // 0..1023
                int m = idx >> 3;          // 0..127
                int j = idx & 7;           // float4 -> klocal j*4
                int grow = bm + m;
                float4 v = make_float4(0.f, 0.f, 0.f, 0.f);
                if (grow < N_NODES)
                    v = *(const float4*)(A_ext + (size_t)grow * F_DIM + k0 + j * 4);
                int o = m * LDA + j * 4;
                *(__half2*)&As[o]     = __floats2half2_rn(v.x, v.y);
                *(__half2*)&As[o + 2] = __floats2half2_rn(v.z, v.w);
            }
        }
        // ---- B tile: 128 n-rows x 32 halves from Wh [n][k] ----
        {
            int idx = tid;                 // 0..255, need 512 uint4 -> 2 each
            #pragma unroll
            for (int l = 0; l < 2; ++l) {
                int id2 = idx + l * 256;
                int n = id2 >> 2;          // 0..127
                int j = id2 & 3;           // uint4 -> klocal j*8
                *(uint4*)&Bs[n * LDA + j * 8] =
                    *(const uint4*)(Wh + (size_t)(bn + n) * F_DIM + k0 + j * 8);
            }
        }
        __syncthreads();

        #pragma unroll
        for (int ks = 0; ks < KCH; ks += 16) {
            uint32_t a[2][4];
            #pragma unroll
            for (int mf = 0; mf < 2; ++mf) {
                uint32_t off = (uint32_t)((wm * 32 + mf * 16 + lanerow) * LDA
                                          + ks + lanek) * 2;
                ldsm4(a[mf][0], a[mf][1], a[mf][2], a[mf][3], sA + off);
            }
            #pragma unroll
            for (int h = 0; h < 2; ++h) {      // two halves of 4 n-tiles
                uint32_t b[4][2];
                #pragma unroll
                for (int g = 0; g < 2; ++g) {  // each x4 covers 2 n-tiles
                    uint32_t off = (uint32_t)((wn * 64 + (h * 2 + g) * 16
                                               + lanerow) * LDA + ks + lanek) * 2;
                    uint32_t r0, r1, r2, r3;
                    ldsm4(r0, r1, r2, r3, sB + off);
                    b[g * 2][0] = r0; b[g * 2][1] = r2;
                    b[g * 2 + 1][0] = r1; b[g * 2 + 1][1] = r3;
                }
                #pragma unroll
                for (int mf = 0; mf < 2; ++mf)
                    #pragma unroll
                    for (int t = 0; t < 4; ++t)
                        mma16816(acc[mf][h * 4 + t], a[mf], b[t]);
            }
        }
        __syncthreads();
    }

    // ---- epilogue: write fp16 g_xt ----
    int qrow = lane >> 2;          // 0..7
    int qcol = (lane & 3) * 2;     // 0,2,4,6
    #pragma unroll
    for (int mf = 0; mf < 2; ++mf) {
        int r0 = bm + wm * 32 + mf * 16 + qrow;
        #pragma unroll
        for (int nt = 0; nt < 8; ++nt) {
            int col = bn + wn * 64 + nt * 8 + qcol;
            float* d = acc[mf][nt];
            if (r0 < N_NODES)
                *(__half2*)(g_xt + (size_t)r0 * F_DIM + col) =
                    __floats2half2_rn(d[0], d[1]);
            if (r0 + 8 < N_NODES)
                *(__half2*)(g_xt + (size_t)(r0 + 8) * F_DIM + col) =
                    __floats2half2_rn(d[2], d[3]);
        }
    }
}

// ---------------- fp16 row helpers ----------------
__device__ __forceinline__ void acc8_from_u4(float* acc, uint4 v) {
    __half2* h = (__half2*)&v;
    #pragma unroll
    for (int i = 0; i < 4; ++i) {
        float2 f = __half22float2(h[i]);
        acc[2 * i]     += f.x;
        acc[2 * i + 1] += f.y;
    }
}
__device__ __forceinline__ uint4 u4_from_8f(const float* s) {
    uint4 v;
    __half2* h = (__half2*)&v;
    #pragma unroll
    for (int i = 0; i < 4; ++i)
        h[i] = __floats2half2_rn(s[2 * i], s[2 * i + 1]);
    return v;
}

// ------- gather node -> hyperedge: g_m[e] = Binv[e] * sum_{src in e} g_xt[src]
__global__ __launch_bounds__(256)
void k_gather_n2e() {
    int w = (blockIdx.x * blockDim.x + threadIdx.x) >> 5;
    if (w >= N_NODES) return;
    int lane = threadIdx.x & 31;
    int off = g_offB[w];
    int deg = g_degB[w];
    const int* __restrict__ adj = g_adjB + off;

    float acc[8] = {0.f, 0.f, 0.f, 0.f, 0.f, 0.f, 0.f, 0.f};
    #pragma unroll 4
    for (int j = 0; j < deg; ++j) {
        int s = __ldg(adj + j);
        uint4 v = __ldg((const uint4*)(g_xt + (size_t)s * F_DIM) + lane);
        acc8_from_u4(acc, v);
    }
    float binv = deg > 0 ? 1.f / (float)deg : 0.f;
    #pragma unroll
    for (int i = 0; i < 8; ++i) acc[i] *= binv;
    *((uint4*)(g_m + (size_t)w * F_DIM) + lane) = u4_from_8f(acc);
}

__device__ __forceinline__ float prelu(float v, float a) {
    return v >= 0.f ? v : a * v;
}

// ------- gather hyperedge -> node, fused epilogue
// use_out: 1 -> write fp32 dout (+x residual), 0 -> write fp16 g_h
__global__ __launch_bounds__(256)
void k_gather_e2n(float* __restrict__ dout, const float* __restrict__ bias,
                  const float* __restrict__ aP, const float* __restrict__ xres,
                  int use_out, int addres) {
    int w = (blockIdx.x * blockDim.x + threadIdx.x) >> 5;
    if (w >= N_NODES) return;
    int lane = threadIdx.x & 31;
    int off = g_offD[w];
    int deg = g_degD[w];
    const int* __restrict__ adj = g_adjD + off;

    float acc[8] = {0.f, 0.f, 0.f, 0.f, 0.f, 0.f, 0.f, 0.f};
    #pragma unroll 4
    for (int j = 0; j < deg; ++j) {
        int e = __ldg(adj + j);
        uint4 v = __ldg((const uint4*)(g_m + (size_t)e * F_DIM) + lane);
        acc8_from_u4(acc, v);
    }
    float dinv = deg > 0 ? 1.f / (float)deg : 0.f;
    float av = __ldg(aP);
    float4 bb0 = *(const float4*)(bias + lane * 8);
    float4 bb1 = *(const float4*)(bias + lane * 8 + 4);
    float r[8];
    r[0] = fmaf(acc[0], dinv, bb0.x); r[1] = fmaf(acc[1], dinv, bb0.y);
    r[2] = fmaf(acc[2], dinv, bb0.z); r[3] = fmaf(acc[3], dinv, bb0.w);
    r[4] = fmaf(acc[4], dinv, bb1.x); r[5] = fmaf(acc[5], dinv, bb1.y);
    r[6] = fmaf(acc[6], dinv, bb1.z); r[7] = fmaf(acc[7], dinv, bb1.w);

    if (addres) {
        const float* xr = xres + (size_t)w * F_DIM + lane * 8;
        float4 x0 = __ldg((const float4*)xr);
        float4 x1 = __ldg((const float4*)(xr + 4));
        r[0] += x0.x; r[1] += x0.y; r[2] += x0.z; r[3] += x0.w;
        r[4] += x1.x; r[5] += x1.y; r[6] += x1.z; r[7] += x1.w;
    }
    #pragma unroll
    for (int i = 0; i < 8; ++i) r[i] = prelu(r[i], av);

    if (use_out) {
        float* dr = dout + (size_t)w * F_DIM + lane * 8;
        *(float4*)dr       = make_float4(r[0], r[1], r[2], r[3]);
        *(float4*)(dr + 4) = make_float4(r[4], r[5], r[6], r[7]);
    } else {
        *((uint4*)(g_h + (size_t)w * F_DIM) + lane) = u4_from_8f(r);
    }
}

// ---------------- launch ----------------
extern "C" void kernel_launch(void* const* d_in, const int* in_sizes, int n_in,
                              void* d_out, int out_size) {
    const float* x  = (const float*)d_in[0];
    const int*   ei = (const int*)  d_in[1];
    const float* W1 = (const float*)d_in[2];
    const float* b1 = (const float*)d_in[3];
    const float* W2 = (const float*)d_in[4];
    const float* b2 = (const float*)d_in[5];
    const float* a  = (const float*)d_in[6];
    float* out = (float*)d_out;

    const int GAT = (N_NODES * 32 + 255) / 256;   // warp per node
    dim3 ggrid(2, (N_NODES + 127) / 128);         // 2 n-tiles x 782 m-tiles

    // ---- CSR build + W prep (shared by both layers) ----
    k_zero_counts<<<(N_NODES + 255) / 256, 256>>>();
    k_count<<<(NNZ + 255) / 256, 256>>>(ei);
    k_scan1<<<dim3(NB1, 2), 1024>>>();
    k_scan2<<<dim3(1, 2), 128>>>();
    k_scan3<<<dim3(NB1, 2), 1024>>>();
    k_fill<<<(NNZ + 255) / 256, 256>>>(ei);
    k_prep_w<<<F_DIM * F_DIM / 256, 256>>>(W1, 0);
    k_prep_w<<<F_DIM * F_DIM / 256, 256>>>(W2, 1);

    // ---- layer 1 ----
    k_gemm_mma<<<ggrid, 256>>>(x, 0, 0);
    k_gather_n2e<<<GAT, 256>>>();
    k_gather_e2n<<<GAT, 256>>>(out, b1, a, x, 0, 0);

    // ---- layer 2 ----
    k_gemm_mma<<<ggrid, 256>>>(x /*unused*/, 1, 1);
    k_gather_n2e<<<GAT, 256>>>();
    k_gather_e2n<<<GAT, 256>>>(out, b2, a, x, 1, 1);
}

// round 9
// speedup vs baseline: 2.7986x; 1.0257x over previous
#include <cuda_runtime.h>
#include <cuda_fp16.h>
#include <cstddef>
#include <cstdint>

#define N_NODES 100000
#define F_DIM   256
#define NNZ     1600000
#define NB1     98          // ceil(N_NODES/1024)

// ---------------- scratch (no allocation allowed) ----------------
// __device__ symbols are ONLY referenced from device code, never passed
// as kernel arguments from host.
__device__ __half g_xt[(size_t)N_NODES * F_DIM];  // GEMM output, fp16 (gathered)
__device__ __half g_m [(size_t)N_NODES * F_DIM];  // hyperedge accum, fp16 (gathered)
__device__ __half g_h [(size_t)N_NODES * F_DIM];  // layer-1 hidden, fp16

__device__ __half g_W1h[F_DIM * F_DIM];  // W1^T f16  [n][k]
__device__ __half g_W2h[F_DIM * F_DIM];  // W2^T f16  [n][k]

__device__ int g_degD[N_NODES];
__device__ int g_degB[N_NODES];
__device__ int g_offD[N_NODES];
__device__ int g_offB[N_NODES];
__device__ int g_curD[N_NODES];
__device__ int g_curB[N_NODES];
__device__ int g_adjD[NNZ];       // grouped by src: stores dst ids
__device__ int g_adjB[NNZ];       // grouped by dst: stores src ids
__device__ int g_bsumD[NB1];
__device__ int g_bsumB[NB1];

// ---------------- CSR build ----------------
__global__ void k_zero_counts() {
    int i = blockIdx.x * blockDim.x + threadIdx.x;
    if (i < N_NODES) { g_degD[i] = 0; g_degB[i] = 0; }
}

__global__ void k_count(const int* __restrict__ ei) {
    int i = blockIdx.x * blockDim.x + threadIdx.x;
    if (i < NNZ) {
        atomicAdd(&g_degD[ei[i]], 1);
        atomicAdd(&g_degB[ei[i + NNZ]], 1);
    }
}

__global__ void k_scan1() {
    int which = blockIdx.y;
    const int* __restrict__ in  = which ? g_degB  : g_degD;
    int* __restrict__ out       = which ? g_offB  : g_offD;
    int* __restrict__ bsums     = which ? g_bsumB : g_bsumD;
    __shared__ int sh[1024];
    int g = blockIdx.x * 1024 + threadIdx.x;
    int v = (g < N_NODES) ? in[g] : 0;
    sh[threadIdx.x] = v;
    __syncthreads();
    #pragma unroll
    for (int off = 1; off < 1024; off <<= 1) {
        int t = (threadIdx.x >= off) ? sh[threadIdx.x - off] : 0;
        __syncthreads();
        sh[threadIdx.x] += t;
        __syncthreads();
    }
    if (g < N_NODES) out[g] = sh[threadIdx.x] - v;   // exclusive
    if (threadIdx.x == 1023) bsums[blockIdx.x] = sh[1023];
}

__global__ void k_scan2() {
    int* __restrict__ bsums = blockIdx.y ? g_bsumB : g_bsumD;
    __shared__ int sh[128];
    int v = (threadIdx.x < NB1) ? bsums[threadIdx.x] : 0;
    sh[threadIdx.x] = v;
    __syncthreads();
    #pragma unroll
    for (int off = 1; off < 128; off <<= 1) {
        int t = (threadIdx.x >= off) ? sh[threadIdx.x - off] : 0;
        __syncthreads();
        sh[threadIdx.x] += t;
        __syncthreads();
    }
    if (threadIdx.x < NB1) bsums[threadIdx.x] = sh[threadIdx.x] - v;
}

__global__ void k_scan3() {
    int which = blockIdx.y;
    int* __restrict__ out         = which ? g_offB  : g_offD;
    const int* __restrict__ bsums = which ? g_bsumB : g_bsumD;
    int* __restrict__ cur         = which ? g_curB  : g_curD;
    int g = blockIdx.x * 1024 + threadIdx.x;
    if (g < N_NODES) {
        int v = out[g] + bsums[blockIdx.x];
        out[g] = v;
        cur[g] = v;
    }
}

__global__ void k_fill(const int* __restrict__ ei) {
    int i = blockIdx.x * blockDim.x + threadIdx.x;
    if (i < NNZ) {
        int s = ei[i], d = ei[i + NNZ];
        g_adjD[atomicAdd(&g_curD[s], 1)] = d;
        g_adjB[atomicAdd(&g_curB[d], 1)] = s;
    }
}

// ---------------- W prep: transpose + f16, both weights in one launch ----
// blockIdx.y: 0 -> W1, 1 -> W2
__global__ void k_prep_w(const float* __restrict__ W1,
                         const float* __restrict__ W2) {
    int which = blockIdx.y;
    const float* __restrict__ W = which ? W2 : W1;
    __half* dh = which ? g_W2h : g_W1h;
    int i = blockIdx.x * blockDim.x + threadIdx.x;   // 65536 per slice
    int k = i >> 8;
    int n = i & 255;
    dh[n * F_DIM + k] = __float2half_rn(W[k * F_DIM + n]);  // coalesced in n
}

// ---------------- HMMA GEMM via mma.sync (portable) ----------------
// g_xt[M,256](fp16) = A[M,256] @ W[256,256], single-pass f16, fp32 accum.
// CTA: 256 threads (8 warps as 4m x 2n), tile 128x128, K chunk 32.
#define KCH 32
#define LDA 40                        // padded row stride (halves)

__device__ __forceinline__ uint32_t smem_u32(const void* p) {
    uint32_t a;
    asm("{ .reg .u64 t; cvta.to.shared.u64 t, %1; cvt.u32.u64 %0, t; }"
        : "=r"(a) : "l"(p));
    return a;
}
__device__ __forceinline__ void ldsm4(uint32_t& r0, uint32_t& r1,
                                      uint32_t& r2, uint32_t& r3, uint32_t a) {
    asm volatile("ldmatrix.sync.aligned.m8n8.x4.shared.b16 {%0,%1,%2,%3}, [%4];"
                 : "=r"(r0), "=r"(r1), "=r"(r2), "=r"(r3) : "r"(a));
}
__device__ __forceinline__ void mma16816(float* d, const uint32_t* a,
                                         const uint32_t* b) {
    asm volatile(
        "mma.sync.aligned.m16n8k16.row.col.f32.f16.f16.f32 "
        "{%0,%1,%2,%3},{%4,%5,%6,%7},{%8,%9},{%0,%1,%2,%3};"
        : "+f"(d[0]), "+f"(d[1]), "+f"(d[2]), "+f"(d[3])
        : "r"(a[0]), "r"(a[1]), "r"(a[2]), "r"(a[3]), "r"(b[0]), "r"(b[1]));
}

__global__ __launch_bounds__(256, 2)
void k_gemm_mma(const float* __restrict__ A_ext, int use_h, int use_w2) {
    __shared__ __half As[128 * LDA];
    __shared__ __half Bs[128 * LDA];

    const __half* __restrict__ Wh = use_w2 ? g_W2h : g_W1h;

    int tid  = threadIdx.x;
    int wid  = tid >> 5;
    int lane = tid & 31;
    int wm   = wid & 3;        // warp m index (4) -> rows wm*32
    int wn   = wid >> 2;       // warp n index (2) -> cols wn*64
    int bm   = blockIdx.y * 128;
    int bn   = blockIdx.x * 128;

    uint32_t sA = smem_u32(As);
    uint32_t sB = smem_u32(Bs);

    float acc[2][8][4];
    #pragma unroll
    for (int i = 0; i < 2; ++i)
        #pragma unroll
        for (int j = 0; j < 8; ++j)
            #pragma unroll
            for (int c = 0; c < 4; ++c) acc[i][j][c] = 0.f;

    int lanerow = lane & 15;
    int lanek   = (lane >> 4) << 3;   // 0 or 8

    for (int k0 = 0; k0 < F_DIM; k0 += KCH) {
        // ---- A tile: 128 rows x 32 halves ----
        if (use_h) {
            #pragma unroll
            for (int l = 0; l < 2; ++l) {
                int idx = tid + l * 256;   // 0..511
                int m = idx >> 2;          // 0..127
                int j = idx & 3;           // uint4 -> klocal j*8
                int grow = bm + m;
                uint4 v = make_uint4(0u, 0u, 0u, 0u);
                if (grow < N_NODES)
                    v = *(const uint4*)(g_h + (size_t)grow * F_DIM + k0 + j * 8);
                *(uint4*)&As[m * LDA + j * 8] = v;
            }
        } else {
            #pragma unroll
            for (int l = 0; l < 4; ++l) {
                int idx = tid + l * 256;   // 0..1023
                int m = idx >> 3;          // 0..127
                int j = idx & 7;           // float4 -> klocal j*4
                int grow = bm + m;
                float4 v = make_float4(0.f, 0.f, 0.f, 0.f);
                if (grow < N_NODES)
                    v = *(const float4*)(A_ext + (size_t)grow * F_DIM + k0 + j * 4);
                int o = m * LDA + j * 4;
                *(__half2*)&As[o]     = __floats2half2_rn(v.x, v.y);
                *(__half2*)&As[o + 2] = __floats2half2_rn(v.z, v.w);
            }
        }
        // ---- B tile: 128 n-rows x 32 halves from Wh [n][k] ----
        {
            #pragma unroll
            for (int l = 0; l < 2; ++l) {
                int id2 = tid + l * 256;
                int n = id2 >> 2;          // 0..127
                int j = id2 & 3;           // uint4 -> klocal j*8
                *(uint4*)&Bs[n * LDA + j * 8] =
                    *(const uint4*)(Wh + (size_t)(bn + n) * F_DIM + k0 + j * 8);
            }
        }
        __syncthreads();

        #pragma unroll
        for (int ks = 0; ks < KCH; ks += 16) {
            uint32_t a[2][4];
            #pragma unroll
            for (int mf = 0; mf < 2; ++mf) {
                uint32_t off = (uint32_t)((wm * 32 + mf * 16 + lanerow) * LDA
                                          + ks + lanek) * 2;
                ldsm4(a[mf][0], a[mf][1], a[mf][2], a[mf][3], sA + off);
            }
            #pragma unroll
            for (int h = 0; h < 2; ++h) {      // two halves of 4 n-tiles
                uint32_t b[4][2];
                #pragma unroll
                for (int g = 0; g < 2; ++g) {  // each x4 covers 2 n-tiles
                    uint32_t off = (uint32_t)((wn * 64 + (h * 2 + g) * 16
                                               + lanerow) * LDA + ks + lanek) * 2;
                    uint32_t r0, r1, r2, r3;
                    ldsm4(r0, r1, r2, r3, sB + off);
                    b[g * 2][0] = r0; b[g * 2][1] = r2;
                    b[g * 2 + 1][0] = r1; b[g * 2 + 1][1] = r3;
                }
                #pragma unroll
                for (int mf = 0; mf < 2; ++mf)
                    #pragma unroll
                    for (int t = 0; t < 4; ++t)
                        mma16816(acc[mf][h * 4 + t], a[mf], b[t]);
            }
        }
        __syncthreads();
    }

    // ---- epilogue: write fp16 g_xt ----
    int qrow = lane >> 2;          // 0..7
    int qcol = (lane & 3) * 2;     // 0,2,4,6
    #pragma unroll
    for (int mf = 0; mf < 2; ++mf) {
        int r0 = bm + wm * 32 + mf * 16 + qrow;
        #pragma unroll
        for (int nt = 0; nt < 8; ++nt) {
            int col = bn + wn * 64 + nt * 8 + qcol;
            float* d = acc[mf][nt];
            if (r0 < N_NODES)
                *(__half2*)(g_xt + (size_t)r0 * F_DIM + col) =
                    __floats2half2_rn(d[0], d[1]);
            if (r0 + 8 < N_NODES)
                *(__half2*)(g_xt + (size_t)(r0 + 8) * F_DIM + col) =
                    __floats2half2_rn(d[2], d[3]);
        }
    }
}

// ---------------- fp16 row helpers ----------------
__device__ __forceinline__ void acc8_from_u4(float* acc, uint4 v) {
    __half2* h = (__half2*)&v;
    #pragma unroll
    for (int i = 0; i < 4; ++i) {
        float2 f = __half22float2(h[i]);
        acc[2 * i]     += f.x;
        acc[2 * i + 1] += f.y;
    }
}
__device__ __forceinline__ uint4 u4_from_8f(const float* s) {
    uint4 v;
    __half2* h = (__half2*)&v;
    #pragma unroll
    for (int i = 0; i < 4; ++i)
        h[i] = __floats2half2_rn(s[2 * i], s[2 * i + 1]);
    return v;
}

// ------- gather node -> hyperedge: g_m[e] = Binv[e] * sum_{src in e} g_xt[src]
__global__ __launch_bounds__(256)
void k_gather_n2e() {
    int w = (blockIdx.x * blockDim.x + threadIdx.x) >> 5;
    if (w >= N_NODES) return;
    int lane = threadIdx.x & 31;
    int off = g_offB[w];
    int deg = g_degB[w];
    const int* __restrict__ adj = g_adjB + off;

    float acc[8] = {0.f, 0.f, 0.f, 0.f, 0.f, 0.f, 0.f, 0.f};
    #pragma unroll 4
    for (int j = 0; j < deg; ++j) {
        int s = __ldg(adj + j);
        uint4 v = __ldg((const uint4*)(g_xt + (size_t)s * F_DIM) + lane);
        acc8_from_u4(acc, v);
    }
    float binv = deg > 0 ? 1.f / (float)deg : 0.f;
    #pragma unroll
    for (int i = 0; i < 8; ++i) acc[i] *= binv;
    *((uint4*)(g_m + (size_t)w * F_DIM) + lane) = u4_from_8f(acc);
}

__device__ __forceinline__ float prelu(float v, float a) {
    return v >= 0.f ? v : a * v;
}

// ------- gather hyperedge -> node, fused epilogue
// use_out: 1 -> write fp32 dout (+x residual), 0 -> write fp16 g_h
__global__ __launch_bounds__(256)
void k_gather_e2n(float* __restrict__ dout, const float* __restrict__ bias,
                  const float* __restrict__ aP, const float* __restrict__ xres,
                  int use_out, int addres) {
    int w = (blockIdx.x * blockDim.x + threadIdx.x) >> 5;
    if (w >= N_NODES) return;
    int lane = threadIdx.x & 31;
    int off = g_offD[w];
    int deg = g_degD[w];
    const int* __restrict__ adj = g_adjD + off;

    float acc[8] = {0.f, 0.f, 0.f, 0.f, 0.f, 0.f, 0.f, 0.f};
    #pragma unroll 4
    for (int j = 0; j < deg; ++j) {
        int e = __ldg(adj + j);
        uint4 v = __ldg((const uint4*)(g_m + (size_t)e * F_DIM) + lane);
        acc8_from_u4(acc, v);
    }
    float dinv = deg > 0 ? 1.f / (float)deg : 0.f;
    float av = __ldg(aP);
    float4 bb0 = *(const float4*)(bias + lane * 8);
    float4 bb1 = *(const float4*)(bias + lane * 8 + 4);
    float r[8];
    r[0] = fmaf(acc[0], dinv, bb0.x); r[1] = fmaf(acc[1], dinv, bb0.y);
    r[2] = fmaf(acc[2], dinv, bb0.z); r[3] = fmaf(acc[3], dinv, bb0.w);
    r[4] = fmaf(acc[4], dinv, bb1.x); r[5] = fmaf(acc[5], dinv, bb1.y);
    r[6] = fmaf(acc[6], dinv, bb1.z); r[7] = fmaf(acc[7], dinv, bb1.w);

    if (addres) {
        const float* xr = xres + (size_t)w * F_DIM + lane * 8;
        float4 x0 = __ldg((const float4*)xr);
        float4 x1 = __ldg((const float4*)(xr + 4));
        r[0] += x0.x; r[1] += x0.y; r[2] += x0.z; r[3] += x0.w;
        r[4] += x1.x; r[5] += x1.y; r[6] += x1.z; r[7] += x1.w;
    }
    #pragma unroll
    for (int i = 0; i < 8; ++i) r[i] = prelu(r[i], av);

    if (use_out) {
        float* dr = dout + (size_t)w * F_DIM + lane * 8;
        *(float4*)dr       = make_float4(r[0], r[1], r[2], r[3]);
        *(float4*)(dr + 4) = make_float4(r[4], r[5], r[6], r[7]);
    } else {
        *((uint4*)(g_h + (size_t)w * F_DIM) + lane) = u4_from_8f(r);
    }
}

// ---------------- launch ----------------
extern "C" void kernel_launch(void* const* d_in, const int* in_sizes, int n_in,
                              void* d_out, int out_size) {
    const float* x  = (const float*)d_in[0];
    const int*   ei = (const int*)  d_in[1];
    const float* W1 = (const float*)d_in[2];
    const float* b1 = (const float*)d_in[3];
    const float* W2 = (const float*)d_in[4];
    const float* b2 = (const float*)d_in[5];
    const float* a  = (const float*)d_in[6];
    float* out = (float*)d_out;

    // Host-side objects created once (no device memory involved). The launched
    // work is identical on every call.
    static cudaStream_t s_side = [] {
        cudaStream_t s = nullptr;
        cudaStreamCreateWithFlags(&s, cudaStreamNonBlocking);
        return s;
    }();
    static cudaEvent_t e_fork = [] {
        cudaEvent_t e = nullptr;
        cudaEventCreateWithFlags(&e, cudaEventDisableTiming);
        return e;
    }();
    static cudaEvent_t e_join = [] {
        cudaEvent_t e = nullptr;
        cudaEventCreateWithFlags(&e, cudaEventDisableTiming);
        return e;
    }();

    const int GAT = (N_NODES * 32 + 255) / 256;   // warp per node
    dim3 ggrid(2, (N_NODES + 127) / 128);         // 2 n-tiles x 782 m-tiles

    // ---- fork: W prep + GEMM-1 on side stream, CSR build on main ----
    cudaEventRecord(e_fork, 0);
    cudaStreamWaitEvent(s_side, e_fork, 0);

    // side stream: independent of edge_index
    k_prep_w<<<dim3(F_DIM * F_DIM / 256, 2), 256, 0, s_side>>>(W1, W2);
    k_gemm_mma<<<ggrid, 256, 0, s_side>>>(x, 0, 0);
    cudaEventRecord(e_join, s_side);

    // main stream: CSR build (independent of weights/features)
    k_zero_counts<<<(N_NODES + 255) / 256, 256>>>();
    k_count<<<(NNZ + 255) / 256, 256>>>(ei);
    k_scan1<<<dim3(NB1, 2), 1024>>>();
    k_scan2<<<dim3(1, 2), 128>>>();
    k_scan3<<<dim3(NB1, 2), 1024>>>();
    k_fill<<<(NNZ + 255) / 256, 256>>>(ei);

    // join: gathers need both CSR and GEMM-1 output
    cudaStreamWaitEvent(0, e_join, 0);

    // ---- layer 1 ----
    k_gather_n2e<<<GAT, 256>>>();
    k_gather_e2n<<<GAT, 256>>>(out, b1, a, x, 0, 0);

    // ---- layer 2 ----
    k_gemm_mma<<<ggrid, 256>>>(x /*unused*/, 1, 1);
    k_gather_n2e<<<GAT, 256>>>();
    k_gather_e2n<<<GAT, 256>>>(out, b2, a, x, 1, 1);
}

// round 10
// speedup vs baseline: 2.8127x; 1.0050x over previous
#include <cuda_runtime.h>
#include <cuda_fp16.h>
#include <cstddef>
#include <cstdint>

#define N_NODES 100000
#define F_DIM   256
#define NNZ     1600000
#define NB1     98          // ceil(N_NODES/1024)

// ---------------- scratch (no allocation allowed) ----------------
// __device__ symbols are ONLY referenced from device code, never passed
// as kernel arguments from host.
__device__ __half g_xt[(size_t)N_NODES * F_DIM];  // GEMM output, fp16 (gathered)
__device__ __half g_m [(size_t)N_NODES * F_DIM];  // hyperedge accum, fp16 (gathered)
__device__ __half g_h [(size_t)N_NODES * F_DIM];  // layer-1 hidden, fp16

__device__ __half g_W1h[F_DIM * F_DIM];  // W1^T f16  [n][k]
__device__ __half g_W2h[F_DIM * F_DIM];  // W2^T f16  [n][k]

__device__ int g_degD[N_NODES];
__device__ int g_degB[N_NODES];
__device__ int g_offD[N_NODES];
__device__ int g_offB[N_NODES];
__device__ int g_curD[N_NODES];
__device__ int g_curB[N_NODES];
__device__ int g_adjD[NNZ];       // grouped by src: stores dst ids
__device__ int g_adjB[NNZ];       // grouped by dst: stores src ids
__device__ int g_bsumD[NB1];
__device__ int g_bsumB[NB1];

// ---------------- CSR build ----------------
__global__ void k_zero_counts() {
    int i = blockIdx.x * blockDim.x + threadIdx.x;
    if (i < N_NODES) { g_degD[i] = 0; g_degB[i] = 0; }
}

// 2 edges per thread via int2 loads on each half
__global__ void k_count(const int* __restrict__ ei) {
    int i = blockIdx.x * blockDim.x + threadIdx.x;
    if (i < NNZ / 2) {
        int2 s2 = ((const int2*)ei)[i];
        int2 d2 = ((const int2*)(ei + NNZ))[i];
        atomicAdd(&g_degD[s2.x], 1);
        atomicAdd(&g_degD[s2.y], 1);
        atomicAdd(&g_degB[d2.x], 1);
        atomicAdd(&g_degB[d2.y], 1);
    }
}

__global__ void k_scan1() {
    int which = blockIdx.y;
    const int* __restrict__ in  = which ? g_degB  : g_degD;
    int* __restrict__ out       = which ? g_offB  : g_offD;
    int* __restrict__ bsums     = which ? g_bsumB : g_bsumD;
    __shared__ int sh[1024];
    int g = blockIdx.x * 1024 + threadIdx.x;
    int v = (g < N_NODES) ? in[g] : 0;
    sh[threadIdx.x] = v;
    __syncthreads();
    #pragma unroll
    for (int off = 1; off < 1024; off <<= 1) {
        int t = (threadIdx.x >= off) ? sh[threadIdx.x - off] : 0;
        __syncthreads();
        sh[threadIdx.x] += t;
        __syncthreads();
    }
    if (g < N_NODES) out[g] = sh[threadIdx.x] - v;   // exclusive
    if (threadIdx.x == 1023) bsums[blockIdx.x] = sh[1023];
}

__global__ void k_scan2() {
    int* __restrict__ bsums = blockIdx.y ? g_bsumB : g_bsumD;
    __shared__ int sh[128];
    int v = (threadIdx.x < NB1) ? bsums[threadIdx.x] : 0;
    sh[threadIdx.x] = v;
    __syncthreads();
    #pragma unroll
    for (int off = 1; off < 128; off <<= 1) {
        int t = (threadIdx.x >= off) ? sh[threadIdx.x - off] : 0;
        __syncthreads();
        sh[threadIdx.x] += t;
        __syncthreads();
    }
    if (threadIdx.x < NB1) bsums[threadIdx.x] = sh[threadIdx.x] - v;
}

__global__ void k_scan3() {
    int which = blockIdx.y;
    int* __restrict__ out         = which ? g_offB  : g_offD;
    const int* __restrict__ bsums = which ? g_bsumB : g_bsumD;
    int* __restrict__ cur         = which ? g_curB  : g_curD;
    int g = blockIdx.x * 1024 + threadIdx.x;
    if (g < N_NODES) {
        int v = out[g] + bsums[blockIdx.x];
        out[g] = v;
        cur[g] = v;
    }
}

// fill only the dst-grouped CSR (needed by gather_n2e) — critical path
__global__ void k_fillB(const int* __restrict__ ei) {
    int i = blockIdx.x * blockDim.x + threadIdx.x;
    if (i < NNZ) {
        int s = ei[i], d = ei[i + NNZ];
        g_adjB[atomicAdd(&g_curB[d], 1)] = s;
    }
}

// fill the src-grouped CSR (needed by gather_e2n) — overlapped off-path
__global__ void k_fillD(const int* __restrict__ ei) {
    int i = blockIdx.x * blockDim.x + threadIdx.x;
    if (i < NNZ) {
        int s = ei[i], d = ei[i + NNZ];
        g_adjD[atomicAdd(&g_curD[s], 1)] = d;
    }
}

// ---------------- W prep: transpose + f16, both weights in one launch ----
// blockIdx.y: 0 -> W1, 1 -> W2
__global__ void k_prep_w(const float* __restrict__ W1,
                         const float* __restrict__ W2) {
    int which = blockIdx.y;
    const float* __restrict__ W = which ? W2 : W1;
    __half* dh = which ? g_W2h : g_W1h;
    int i = blockIdx.x * blockDim.x + threadIdx.x;   // 65536 per slice
    int k = i >> 8;
    int n = i & 255;
    dh[n * F_DIM + k] = __float2half_rn(W[k * F_DIM + n]);  // coalesced in n
}

// ---------------- HMMA GEMM via mma.sync (portable) ----------------
// g_xt[M,256](fp16) = A[M,256] @ W[256,256], single-pass f16, fp32 accum.
// CTA: 256 threads (8 warps as 4m x 2n), tile 128x128, K chunk 32.
#define KCH 32
#define LDA 40                        // padded row stride (halves)

__device__ __forceinline__ uint32_t smem_u32(const void* p) {
    uint32_t a;
    asm("{ .reg .u64 t; cvta.to.shared.u64 t, %1; cvt.u32.u64 %0, t; }"
        : "=r"(a) : "l"(p));
    return a;
}
__device__ __forceinline__ void ldsm4(uint32_t& r0, uint32_t& r1,
                                      uint32_t& r2, uint32_t& r3, uint32_t a) {
    asm volatile("ldmatrix.sync.aligned.m8n8.x4.shared.b16 {%0,%1,%2,%3}, [%4];"
                 : "=r"(r0), "=r"(r1), "=r"(r2), "=r"(r3) : "r"(a));
}
__device__ __forceinline__ void mma16816(float* d, const uint32_t* a,
                                         const uint32_t* b) {
    asm volatile(
        "mma.sync.aligned.m16n8k16.row.col.f32.f16.f16.f32 "
        "{%0,%1,%2,%3},{%4,%5,%6,%7},{%8,%9},{%0,%1,%2,%3};"
        : "+f"(d[0]), "+f"(d[1]), "+f"(d[2]), "+f"(d[3])
        : "r"(a[0]), "r"(a[1]), "r"(a[2]), "r"(a[3]), "r"(b[0]), "r"(b[1]));
}

__global__ __launch_bounds__(256, 2)
void k_gemm_mma(const float* __restrict__ A_ext, int use_h, int use_w2) {
    __shared__ __half As[128 * LDA];
    __shared__ __half Bs[128 * LDA];

    const __half* __restrict__ Wh = use_w2 ? g_W2h : g_W1h;

    int tid  = threadIdx.x;
    int wid  = tid >> 5;
    int lane = tid & 31;
    int wm   = wid & 3;        // warp m index (4) -> rows wm*32
    int wn   = wid >> 2;       // warp n index (2) -> cols wn*64
    int bm   = blockIdx.y * 128;
    int bn   = blockIdx.x * 128;

    uint32_t sA = smem_u32(As);
    uint32_t sB = smem_u32(Bs);

    float acc[2][8][4];
    #pragma unroll
    for (int i = 0; i < 2; ++i)
        #pragma unroll
        for (int j = 0; j < 8; ++j)
            #pragma unroll
            for (int c = 0; c < 4; ++c) acc[i][j][c] = 0.f;

    int lanerow = lane & 15;
    int lanek   = (lane >> 4) << 3;   // 0 or 8

    for (int k0 = 0; k0 < F_DIM; k0 += KCH) {
        // ---- A tile: 128 rows x 32 halves ----
        if (use_h) {
            #pragma unroll
            for (int l = 0; l < 2; ++l) {
                int idx = tid + l * 256;   // 0..511
                int m = idx >> 2;          // 0..127
                int j = idx & 3;           // uint4 -> klocal j*8
                int grow = bm + m;
                uint4 v = make_uint4(0u, 0u, 0u, 0u);
                if (grow < N_NODES)
                    v = *(const uint4*)(g_h + (size_t)grow * F_DIM + k0 + j * 8);
                *(uint4*)&As[m * LDA + j * 8] = v;
            }
        } else {
            #pragma unroll
            for (int l = 0; l < 4; ++l) {
                int idx = tid + l * 256;   // 0..1023
                int m = idx >> 3;          // 0..127
                int j = idx & 7;           // float4 -> klocal j*4
                int grow = bm + m;
                float4 v = make_float4(0.f, 0.f, 0.f, 0.f);
                if (grow < N_NODES)
                    v = *(const float4*)(A_ext + (size_t)grow * F_DIM + k0 + j * 4);
                int o = m * LDA + j * 4;
                *(__half2*)&As[o]     = __floats2half2_rn(v.x, v.y);
                *(__half2*)&As[o + 2] = __floats2half2_rn(v.z, v.w);
            }
        }
        // ---- B tile: 128 n-rows x 32 halves from Wh [n][k] ----
        {
            #pragma unroll
            for (int l = 0; l < 2; ++l) {
                int id2 = tid + l * 256;
                int n = id2 >> 2;          // 0..127
                int j = id2 & 3;           // uint4 -> klocal j*8
                *(uint4*)&Bs[n * LDA + j * 8] =
                    *(const uint4*)(Wh + (size_t)(bn + n) * F_DIM + k0 + j * 8);
            }
        }
        __syncthreads();

        #pragma unroll
        for (int ks = 0; ks < KCH; ks += 16) {
            uint32_t a[2][4];
            #pragma unroll
            for (int mf = 0; mf < 2; ++mf) {
                uint32_t off = (uint32_t)((wm * 32 + mf * 16 + lanerow) * LDA
                                          + ks + lanek) * 2;
                ldsm4(a[mf][0], a[mf][1], a[mf][2], a[mf][3], sA + off);
            }
            #pragma unroll
            for (int h = 0; h < 2; ++h) {      // two halves of 4 n-tiles
                uint32_t b[4][2];
                #pragma unroll
                for (int g = 0; g < 2; ++g) {  // each x4 covers 2 n-tiles
                    uint32_t off = (uint32_t)((wn * 64 + (h * 2 + g) * 16
                                               + lanerow) * LDA + ks + lanek) * 2;
                    uint32_t r0, r1, r2, r3;
                    ldsm4(r0, r1, r2, r3, sB + off);
                    b[g * 2][0] = r0; b[g * 2][1] = r2;
                    b[g * 2 + 1][0] = r1; b[g * 2 + 1][1] = r3;
                }
                #pragma unroll
                for (int mf = 0; mf < 2; ++mf)
                    #pragma unroll
                    for (int t = 0; t < 4; ++t)
                        mma16816(acc[mf][h * 4 + t], a[mf], b[t]);
            }
        }
        __syncthreads();
    }

    // ---- epilogue: write fp16 g_xt ----
    int qrow = lane >> 2;          // 0..7
    int qcol = (lane & 3) * 2;     // 0,2,4,6
    #pragma unroll
    for (int mf = 0; mf < 2; ++mf) {
        int r0 = bm + wm * 32 + mf * 16 + qrow;
        #pragma unroll
        for (int nt = 0; nt < 8; ++nt) {
            int col = bn + wn * 64 + nt * 8 + qcol;
            float* d = acc[mf][nt];
            if (r0 < N_NODES)
                *(__half2*)(g_xt + (size_t)r0 * F_DIM + col) =
                    __floats2half2_rn(d[0], d[1]);
            if (r0 + 8 < N_NODES)
                *(__half2*)(g_xt + (size_t)(r0 + 8) * F_DIM + col) =
                    __floats2half2_rn(d[2], d[3]);
        }
    }
}

// ---------------- fp16 row helpers ----------------
__device__ __forceinline__ void acc8_from_u4(float* acc, uint4 v) {
    __half2* h = (__half2*)&v;
    #pragma unroll
    for (int i = 0; i < 4; ++i) {
        float2 f = __half22float2(h[i]);
        acc[2 * i]     += f.x;
        acc[2 * i + 1] += f.y;
    }
}
__device__ __forceinline__ uint4 u4_from_8f(const float* s) {
    uint4 v;
    __half2* h = (__half2*)&v;
    #pragma unroll
    for (int i = 0; i < 4; ++i)
        h[i] = __floats2half2_rn(s[2 * i], s[2 * i + 1]);
    return v;
}

// ------- gather node -> hyperedge: g_m[e] = Binv[e] * sum_{src in e} g_xt[src]
__global__ __launch_bounds__(256)
void k_gather_n2e() {
    int w = (blockIdx.x * blockDim.x + threadIdx.x) >> 5;
    if (w >= N_NODES) return;
    int lane = threadIdx.x & 31;
    int off = g_offB[w];
    int deg = g_degB[w];
    const int* __restrict__ adj = g_adjB + off;

    float acc[8] = {0.f, 0.f, 0.f, 0.f, 0.f, 0.f, 0.f, 0.f};
    #pragma unroll 4
    for (int j = 0; j < deg; ++j) {
        int s = __ldg(adj + j);
        uint4 v = __ldg((const uint4*)(g_xt + (size_t)s * F_DIM) + lane);
        acc8_from_u4(acc, v);
    }
    float binv = deg > 0 ? 1.f / (float)deg : 0.f;
    #pragma unroll
    for (int i = 0; i < 8; ++i) acc[i] *= binv;
    *((uint4*)(g_m + (size_t)w * F_DIM) + lane) = u4_from_8f(acc);
}

__device__ __forceinline__ float prelu(float v, float a) {
    return v >= 0.f ? v : a * v;
}

// ------- gather hyperedge -> node, fused epilogue
// use_out: 1 -> write fp32 dout (+x residual), 0 -> write fp16 g_h
__global__ __launch_bounds__(256)
void k_gather_e2n(float* __restrict__ dout, const float* __restrict__ bias,
                  const float* __restrict__ aP, const float* __restrict__ xres,
                  int use_out, int addres) {
    int w = (blockIdx.x * blockDim.x + threadIdx.x) >> 5;
    if (w >= N_NODES) return;
    int lane = threadIdx.x & 31;
    int off = g_offD[w];
    int deg = g_degD[w];
    const int* __restrict__ adj = g_adjD + off;

    float acc[8] = {0.f, 0.f, 0.f, 0.f, 0.f, 0.f, 0.f, 0.f};
    #pragma unroll 4
    for (int j = 0; j < deg; ++j) {
        int e = __ldg(adj + j);
        uint4 v = __ldg((const uint4*)(g_m + (size_t)e * F_DIM) + lane);
        acc8_from_u4(acc, v);
    }
    float dinv = deg > 0 ? 1.f / (float)deg : 0.f;
    float av = __ldg(aP);
    float4 bb0 = *(const float4*)(bias + lane * 8);
    float4 bb1 = *(const float4*)(bias + lane * 8 + 4);
    float r[8];
    r[0] = fmaf(acc[0], dinv, bb0.x); r[1] = fmaf(acc[1], dinv, bb0.y);
    r[2] = fmaf(acc[2], dinv, bb0.z); r[3] = fmaf(acc[3], dinv, bb0.w);
    r[4] = fmaf(acc[4], dinv, bb1.x); r[5] = fmaf(acc[5], dinv, bb1.y);
    r[6] = fmaf(acc[6], dinv, bb1.z); r[7] = fmaf(acc[7], dinv, bb1.w);

    if (addres) {
        const float* xr = xres + (size_t)w * F_DIM + lane * 8;
        float4 x0 = __ldg((const float4*)xr);
        float4 x1 = __ldg((const float4*)(xr + 4));
        r[0] += x0.x; r[1] += x0.y; r[2] += x0.z; r[3] += x0.w;
        r[4] += x1.x; r[5] += x1.y; r[6] += x1.z; r[7] += x1.w;
    }
    #pragma unroll
    for (int i = 0; i < 8; ++i) r[i] = prelu(r[i], av);

    if (use_out) {
        float* dr = dout + (size_t)w * F_DIM + lane * 8;
        *(float4*)dr       = make_float4(r[0], r[1], r[2], r[3]);
        *(float4*)(dr + 4) = make_float4(r[4], r[5], r[6], r[7]);
    } else {
        *((uint4*)(g_h + (size_t)w * F_DIM) + lane) = u4_from_8f(r);
    }
}

// ---------------- launch ----------------
extern "C" void kernel_launch(void* const* d_in, const int* in_sizes, int n_in,
                              void* d_out, int out_size) {
    const float* x  = (const float*)d_in[0];
    const int*   ei = (const int*)  d_in[1];
    const float* W1 = (const float*)d_in[2];
    const float* b1 = (const float*)d_in[3];
    const float* W2 = (const float*)d_in[4];
    const float* b2 = (const float*)d_in[5];
    const float* a  = (const float*)d_in[6];
    float* out = (float*)d_out;

    // Host-side objects created once (no device memory involved). The launched
    // work is identical on every call.
    static cudaStream_t s_side = [] {
        cudaStream_t s = nullptr;
        cudaStreamCreateWithFlags(&s, cudaStreamNonBlocking);
        return s;
    }();
    static cudaStream_t s_fill = [] {
        cudaStream_t s = nullptr;
        cudaStreamCreateWithFlags(&s, cudaStreamNonBlocking);
        return s;
    }();
    static cudaEvent_t e_fork = [] {
        cudaEvent_t e = nullptr;
        cudaEventCreateWithFlags(&e, cudaEventDisableTiming);
        return e;
    }();
    static cudaEvent_t e_gemm1 = [] {
        cudaEvent_t e = nullptr;
        cudaEventCreateWithFlags(&e, cudaEventDisableTiming);
        return e;
    }();
    static cudaEvent_t e_scan = [] {
        cudaEvent_t e = nullptr;
        cudaEventCreateWithFlags(&e, cudaEventDisableTiming);
        return e;
    }();
    static cudaEvent_t e_fillD = [] {
        cudaEvent_t e = nullptr;
        cudaEventCreateWithFlags(&e, cudaEventDisableTiming);
        return e;
    }();

    const int GAT = (N_NODES * 32 + 255) / 256;   // warp per node
    dim3 ggrid(2, (N_NODES + 127) / 128);         // 2 n-tiles x 782 m-tiles

    // ---- fork: W prep + GEMM-1 on side stream ----
    cudaEventRecord(e_fork, 0);
    cudaStreamWaitEvent(s_side, e_fork, 0);
    k_prep_w<<<dim3(F_DIM * F_DIM / 256, 2), 256, 0, s_side>>>(W1, W2);
    k_gemm_mma<<<ggrid, 256, 0, s_side>>>(x, 0, 0);
    cudaEventRecord(e_gemm1, s_side);

    // ---- main stream: CSR build, B-side only on the critical path ----
    k_zero_counts<<<(N_NODES + 255) / 256, 256>>>();
    k_count<<<(NNZ / 2 + 255) / 256, 256>>>(ei);
    k_scan1<<<dim3(NB1, 2), 1024>>>();
    k_scan2<<<dim3(1, 2), 128>>>();
    k_scan3<<<dim3(NB1, 2), 1024>>>();
    cudaEventRecord(e_scan, 0);
    k_fillB<<<(NNZ + 255) / 256, 256>>>(ei);

    // ---- fill D-CSR off the critical path (overlaps gather_n2e) ----
    cudaStreamWaitEvent(s_fill, e_scan, 0);
    k_fillD<<<(NNZ + 255) / 256, 256, 0, s_fill>>>(ei);
    cudaEventRecord(e_fillD, s_fill);

    // join with GEMM-1, then layer-1 gathers
    cudaStreamWaitEvent(0, e_gemm1, 0);
    k_gather_n2e<<<GAT, 256>>>();
    cudaStreamWaitEvent(0, e_fillD, 0);
    k_gather_e2n<<<GAT, 256>>>(out, b1, a, x, 0, 0);

    // ---- layer 2 ----
    k_gemm_mma<<<ggrid, 256>>>(x /*unused*/, 1, 1);
    k_gather_n2e<<<GAT, 256>>>();
    k_gather_e2n<<<GAT, 256>>>(out, b2, a, x, 1, 1);
}